// round 6
// baseline (speedup 1.0000x reference)
#include <cuda_runtime.h>
#include <cstdint>

#define B_ 2048
#define E_ 256
#define H_ 1024
#define V_ 42
#define S_ 100
#define XP 48            // padded x width (V_ 42 -> 48) so all K-tiles are full

// ---------------- persistent device state (no allocations allowed) ----------
__device__ float g_x[B_ * XP];          // softmax output (tf32-rounded), padded
__device__ float g_h0[2][B_ * H_];      // ping-pong hidden layer 0 (tf32-rounded)
__device__ float g_h1[2][B_ * H_];      // ping-pong hidden layer 1 (tf32-rounded)
__device__ float g_c0[B_ * H_];         // cell state fp32
__device__ float g_c1[B_ * H_];
// rna-rounded tf32 weights (rounded once per run; raw-bit truncation is biased!)
__device__ float g_whh0t[4 * H_ * H_];
__device__ float g_wih0t[4 * H_ * XP];  // zero-padded cols 42..47
__device__ float g_whh1t[4 * H_ * H_];
__device__ float g_wih1t[4 * H_ * H_];

// ---------------- helpers ---------------------------------------------------
__device__ __forceinline__ float rnd_tf32(float x) {
    uint32_t u;
    asm("cvt.rna.tf32.f32 %0, %1;" : "=r"(u) : "f"(x));
    return __uint_as_float(u);
}
__device__ __forceinline__ float fsigm(float x) {
    return __fdividef(1.f, 1.f + __expf(-x));
}
__device__ __forceinline__ float ftanh(float x) {
    return __fdividef(2.f, 1.f + __expf(-2.f * x)) - 1.f;
}

// ---------------- weight prep: two arrays per launch (rna-round + pad) ------
__global__ void prep2_kernel(const float* __restrict__ s1, float* __restrict__ d1,
                             int n1, int k1s, int k1d,
                             const float* __restrict__ s2, float* __restrict__ d2,
                             int n2, int k2s, int k2d) {
    int i = blockIdx.x * blockDim.x + threadIdx.x;
    if (i < n1) {
        int r = i / k1d, k = i - r * k1d;
        float v = (k < k1s) ? s1[(size_t)r * k1s + k] : 0.f;
        d1[i] = rnd_tf32(v);
    } else if (i < n1 + n2) {
        int j = i - n1;
        int r = j / k2d, k = j - r * k2d;
        float v = (k < k2s) ? s2[(size_t)r * k2s + k] : 0.f;
        d2[j] = rnd_tf32(v);
    }
}

// ---------------- init: zero state, one-hot start token ---------------------
__global__ void init_kernel() {
    int idx = blockIdx.x * blockDim.x + threadIdx.x;
    if (idx < B_ * H_) {
        g_c0[idx] = 0.f;
        g_c1[idx] = 0.f;
        g_h1[0][idx] = 0.f;
    }
    if (idx < B_ * XP) {
        g_x[idx] = ((idx % XP) == V_ - 1) ? 1.f : 0.f;
    }
}

// ---------------- fc1: h0 = latent @ fc1_w^T + b (one-time, fp32) -----------
__global__ __launch_bounds__(256) void fc1_kernel(
    const float* __restrict__ latent,
    const float* __restrict__ w,
    const float* __restrict__ bias)
{
    __shared__ float As[16][68];
    __shared__ float Ws[16][68];
    const int tid = threadIdx.x;
    const int bm = blockIdx.y * 64, bn = blockIdx.x * 64;
    const int r = tid >> 2, kq = (tid & 3) * 4;
    const int tx = tid & 15, ty = tid >> 4;

    float acc[4][4];
#pragma unroll
    for (int i = 0; i < 4; i++)
#pragma unroll
        for (int j = 0; j < 4; j++) acc[i][j] = 0.f;

    for (int k0 = 0; k0 < E_; k0 += 16) {
        float4 av = *reinterpret_cast<const float4*>(latent + (size_t)(bm + r) * E_ + k0 + kq);
        float4 wv = *reinterpret_cast<const float4*>(w + (size_t)(bn + r) * E_ + k0 + kq);
        __syncthreads();
        As[kq + 0][r] = av.x; As[kq + 1][r] = av.y; As[kq + 2][r] = av.z; As[kq + 3][r] = av.w;
        Ws[kq + 0][r] = wv.x; Ws[kq + 1][r] = wv.y; Ws[kq + 2][r] = wv.z; Ws[kq + 3][r] = wv.w;
        __syncthreads();
#pragma unroll
        for (int kk = 0; kk < 16; kk++) {
            float4 a = *(const float4*)&As[kk][ty * 4];
            float4 b = *(const float4*)&Ws[kk][tx * 4];
            float am[4] = {a.x, a.y, a.z, a.w};
            float bn2[4] = {b.x, b.y, b.z, b.w};
#pragma unroll
            for (int mi = 0; mi < 4; mi++)
#pragma unroll
                for (int ni = 0; ni < 4; ni++)
                    acc[mi][ni] = fmaf(am[mi], bn2[ni], acc[mi][ni]);
        }
    }
    float bv[4];
#pragma unroll
    for (int ni = 0; ni < 4; ni++) bv[ni] = bias[bn + tx * 4 + ni];
#pragma unroll
    for (int mi = 0; mi < 4; mi++) {
        int m = bm + ty * 4 + mi;
#pragma unroll
        for (int ni = 0; ni < 4; ni++)
            g_h0[0][(size_t)m * H_ + bn + tx * 4 + ni] = rnd_tf32(acc[mi][ni] + bv[ni]);
    }
}

// ---------------- TF32 tensor-core gates GEMM + fused LSTM cell --------------
// gates = h_prev @ W1^T + x_in @ W2^T  (K-concat), mma.sync m16n8k8 tf32.
// 4-stage cp.async ring, prefetch distance 3, ONE __syncthreads per k-tile:
//   wait_group -> sync -> issue(kt+3) -> compute(kt)
// issue(kt+3) overwrites stage (kt-1)%4; the sync proves all warps finished
// computing that stage (done at end of iter kt-1), so no race.
#define NSTG 4
#define STG_F (128 * 20)                 // floats per stage per array

template <int K2P, int LAYER>
__global__ __launch_bounds__(256, 2) void gates_mma(
    int p,
    const float* __restrict__ W1,    // prepped w_hh [4H, 1024]
    const float* __restrict__ W2,    // prepped w_ih [4H, K2P]
    const float* __restrict__ bih,
    const float* __restrict__ bhh)
{
    constexpr int T1 = H_ / 16;
    constexpr int T2 = K2P / 16;
    constexpr int T = T1 + T2;

    const float* A1;
    const float* A2;
    float* cbuf;
    float* hout;
    if (LAYER == 0) { A1 = g_h0[p]; A2 = g_x;          cbuf = g_c0; hout = g_h0[p ^ 1]; }
    else            { A1 = g_h1[p]; A2 = g_h0[p ^ 1];  cbuf = g_c1; hout = g_h1[p ^ 1]; }
    const int strideA2 = (LAYER == 0) ? XP : H_;

    extern __shared__ float sm[];
    float (*As)[128][20] = reinterpret_cast<float (*)[128][20]>(sm);
    float (*Bs)[128][20] = reinterpret_cast<float (*)[128][20]>(sm + NSTG * STG_F);

    const int tid = threadIdx.x;
    const int bm = blockIdx.y * 128;
    const int bn = blockIdx.x * 32;

    // ---- loader mapping: 2 threads per row, 2x 16B cp.async each ----
    const int lrow = tid >> 1;           // 0..127
    const int lkq = (tid & 1) * 8;       // 0 or 8
    const int wrow = (lrow & 3) * H_ + bn + (lrow >> 2);   // j = nl*4+g -> W row
    const float* aRow1 = A1 + (size_t)(bm + lrow) * H_;
    const float* aRow2 = A2 + (size_t)(bm + lrow) * strideA2;
    const float* bRow1 = W1 + (size_t)wrow * H_;
    const float* bRow2 = W2 + (size_t)wrow * K2P;

    auto issue = [&](int kt) {
        const int buf = kt & (NSTG - 1);
        const float* as;
        const float* bs;
        if (kt < T1) { int k = kt * 16 + lkq;        as = aRow1 + k; bs = bRow1 + k; }
        else         { int k = (kt - T1) * 16 + lkq; as = aRow2 + k; bs = bRow2 + k; }
        uint32_t da = (uint32_t)__cvta_generic_to_shared(&As[buf][lrow][lkq]);
        uint32_t db = (uint32_t)__cvta_generic_to_shared(&Bs[buf][lrow][lkq]);
        asm volatile(
            "cp.async.ca.shared.global [%0], [%1], 16;\n\t"
            "cp.async.ca.shared.global [%2], [%3], 16;\n\t"
            "cp.async.ca.shared.global [%4], [%5], 16;\n\t"
            "cp.async.ca.shared.global [%6], [%7], 16;\n\t"
            "cp.async.commit_group;\n\t"
            :: "r"(da), "l"(as), "r"(da + 16), "l"(as + 4),
               "r"(db), "l"(bs), "r"(db + 16), "l"(bs + 4)
            : "memory");
    };

    // ---- mma mapping ----
    const int lane = tid & 31;
    const int wid = tid >> 5;
    const int wm = wid & 1;              // 2 warps over m (64 rows each)
    const int wj = wid >> 1;             // 4 warps over j (32 cols each)
    const int gid = lane >> 2, tig = lane & 3;

    float acc[4][4][4];
#pragma unroll
    for (int a = 0; a < 4; a++)
#pragma unroll
        for (int b = 0; b < 4; b++)
#pragma unroll
            for (int c = 0; c < 4; c++) acc[a][b][c] = 0.f;

    issue(0);
    issue(1);
    issue(2);

    for (int kt = 0; kt < T; ++kt) {
        const int buf = kt & (NSTG - 1);
        if (kt + 3 < T) {
            asm volatile("cp.async.wait_group 2;" ::: "memory");
            __syncthreads();
            issue(kt + 3);
        } else if (kt == T - 3) {
            asm volatile("cp.async.wait_group 2;" ::: "memory");
            __syncthreads();
        } else if (kt == T - 2) {
            asm volatile("cp.async.wait_group 1;" ::: "memory");
            __syncthreads();
        } else {
            asm volatile("cp.async.wait_group 0;" ::: "memory");
            __syncthreads();
        }
#pragma unroll
        for (int h8 = 0; h8 < 2; h8++) {
            const int ko = h8 * 8 + tig;
            uint32_t a[4][4], b[4][2];
#pragma unroll
            for (int mt = 0; mt < 4; mt++) {
                const int m0 = wm * 64 + mt * 16 + gid;
                a[mt][0] = __float_as_uint(As[buf][m0][ko]);
                a[mt][1] = __float_as_uint(As[buf][m0 + 8][ko]);
                a[mt][2] = __float_as_uint(As[buf][m0][ko + 4]);
                a[mt][3] = __float_as_uint(As[buf][m0 + 8][ko + 4]);
            }
#pragma unroll
            for (int nt = 0; nt < 4; nt++) {
                const int j0 = wj * 32 + nt * 8 + gid;
                b[nt][0] = __float_as_uint(Bs[buf][j0][ko]);
                b[nt][1] = __float_as_uint(Bs[buf][j0][ko + 4]);
            }
#pragma unroll
            for (int mt = 0; mt < 4; mt++)
#pragma unroll
                for (int nt = 0; nt < 4; nt++)
                    asm volatile(
                        "mma.sync.aligned.m16n8k8.row.col.f32.tf32.tf32.f32 "
                        "{%0,%1,%2,%3}, {%4,%5,%6,%7}, {%8,%9}, {%0,%1,%2,%3};"
                        : "+f"(acc[mt][nt][0]), "+f"(acc[mt][nt][1]),
                          "+f"(acc[mt][nt][2]), "+f"(acc[mt][nt][3])
                        : "r"(a[mt][0]), "r"(a[mt][1]), "r"(a[mt][2]), "r"(a[mt][3]),
                          "r"(b[nt][0]), "r"(b[nt][1]));
        }
    }

    // ---- fused LSTM cell epilogue via lane-pair shuffle ----
    // tig even lanes ("A") hold (i_pre, f_pre); odd ("B") hold (g_pre, o_pre)
    const bool isA = (tig & 1) == 0;
    const int gl = (tig & 1) * 2;
#pragma unroll
    for (int nt = 0; nt < 4; nt++) {
        const int col = bn + wj * 8 + nt * 2 + (tig >> 1);
        const float bias0 = bih[gl * H_ + col] + bhh[gl * H_ + col];
        const float bias1 = bih[(gl + 1) * H_ + col] + bhh[(gl + 1) * H_ + col];
#pragma unroll
        for (int mt = 0; mt < 4; mt++) {
#pragma unroll
            for (int rh = 0; rh < 2; rh++) {
                const int m = bm + wm * 64 + mt * 16 + gid + rh * 8;
                const size_t off = (size_t)m * H_ + col;
                const float p0 = acc[mt][nt][rh * 2 + 0] + bias0;  // A: i, B: g
                const float p1 = acc[mt][nt][rh * 2 + 1] + bias1;  // A: f, B: o
                const float e = __expf(isA ? -p0 : -2.f * p0);
                const float q0 = __fdividef(isA ? 1.f : 2.f, 1.f + e) - (isA ? 0.f : 1.f);
                const float q1 = fsigm(p1);                        // A: sig(f), B: sig(o)
                const float partner = __shfl_xor_sync(0xffffffffu, q0, 1); // A gets tanh(g)
                const float cold = isA ? cbuf[off] : 0.f;
                const float cn = fmaf(q1, cold, q0 * partner);     // A: sf*c + si*tg
                const float th = ftanh(cn);
                const float th2 = __shfl_xor_sync(0xffffffffu, th, 1);     // B gets tanh(c_new)
                if (isA) cbuf[off] = cn;
                else     hout[off] = rnd_tf32(q1 * th2);           // B: sig(o)*tanh(c_new)
            }
        }
    }
}

// ---------------- logits + softmax feedback ---------------------------------
#define LB 16
#define KC 64
__global__ __launch_bounds__(256) void logits_kernel(
    int p, int t,
    const float* __restrict__ w,     // fc2_w [V, H]
    const float* __restrict__ bias,  // fc2_b [V]
    float* __restrict__ out)         // [B, S, V]
{
    const float* h = g_h1[p ^ 1];
    __shared__ float hs[LB][KC + 1];
    __shared__ float ws[KC][48];
    __shared__ float ls[LB][48];
    const int tid = threadIdx.x;
    const int b0 = blockIdx.x * LB;
    const int r = tid >> 4, q = tid & 15;

    float acc0 = 0.f, acc1 = 0.f, acc2 = 0.f;
    for (int k0 = 0; k0 < H_; k0 += KC) {
        __syncthreads();
#pragma unroll
        for (int i = 0; i < 4; i++) {
            int idx = tid + i * 256;
            int rr = idx >> 6, kk = idx & 63;
            hs[rr][kk] = h[(size_t)(b0 + rr) * H_ + k0 + kk];
        }
        for (int idx = tid; idx < KC * V_; idx += 256) {
            int kk = idx / V_, v = idx - kk * V_;
            ws[kk][v] = w[(size_t)v * H_ + k0 + kk];
        }
        for (int idx = tid; idx < KC * (48 - V_); idx += 256) {
            int kk = idx / (48 - V_);
            ws[kk][V_ + idx % (48 - V_)] = 0.f;
        }
        __syncthreads();
#pragma unroll
        for (int kk = 0; kk < KC; kk++) {
            float a = hs[r][kk];
            acc0 = fmaf(a, ws[kk][q], acc0);
            acc1 = fmaf(a, ws[kk][q + 16], acc1);
            acc2 = fmaf(a, ws[kk][q + 32], acc2);   // pad cols are 0
        }
    }
    const int b = b0 + r;
    const size_t ob = (size_t)b * S_ * V_ + (size_t)t * V_;
    float l0 = acc0 + bias[q];
    float l1 = acc1 + bias[q + 16];
    ls[r][q] = l0;      out[ob + q] = l0;
    ls[r][q + 16] = l1; out[ob + q + 16] = l1;
    if (q + 32 < V_) {
        float l2 = acc2 + bias[q + 32];
        ls[r][q + 32] = l2;
        out[ob + q + 32] = l2;
    }
    __syncthreads();
    if (tid < LB) {
        float mx = -1e30f;
#pragma unroll
        for (int v = 0; v < V_; v++) mx = fmaxf(mx, ls[tid][v]);
        float ev[V_];
        float sum = 0.f;
#pragma unroll
        for (int v = 0; v < V_; v++) {
            ev[v] = __expf(ls[tid][v] - mx);
            sum += ev[v];
        }
        float inv = __fdividef(1.f, sum);
        const int bb = b0 + tid;
#pragma unroll
        for (int v = 0; v < V_; v++)
            g_x[(size_t)bb * XP + v] = rnd_tf32(ev[v] * inv);
    }
}

// ---------------- driver ----------------------------------------------------
extern "C" void kernel_launch(void* const* d_in, const int* in_sizes, int n_in,
                              void* d_out, int out_size)
{
    const float* latent = (const float*)d_in[0];
    const float* fc1_w  = (const float*)d_in[1];
    const float* fc1_b  = (const float*)d_in[2];
    const float* fc2_w  = (const float*)d_in[3];
    const float* fc2_b  = (const float*)d_in[4];
    const float* w_ih0  = (const float*)d_in[5];
    const float* w_hh0  = (const float*)d_in[6];
    const float* b_ih0  = (const float*)d_in[7];
    const float* b_hh0  = (const float*)d_in[8];
    const float* w_ih1  = (const float*)d_in[9];
    const float* w_hh1  = (const float*)d_in[10];
    const float* b_ih1  = (const float*)d_in[11];
    const float* b_hh1  = (const float*)d_in[12];
    float* out = (float*)d_out;

    float* whh0t; cudaGetSymbolAddress((void**)&whh0t, g_whh0t);
    float* wih0t; cudaGetSymbolAddress((void**)&wih0t, g_wih0t);
    float* whh1t; cudaGetSymbolAddress((void**)&whh1t, g_whh1t);
    float* wih1t; cudaGetSymbolAddress((void**)&wih1t, g_wih1t);

    // unconditional every call (no static guards allowed); idempotent non-stream API
    const int smem_bytes = NSTG * STG_F * 2 * (int)sizeof(float);  // 80 KB
    cudaFuncSetAttribute(gates_mma<XP, 0>,
                         cudaFuncAttributeMaxDynamicSharedMemorySize, smem_bytes);
    cudaFuncSetAttribute(gates_mma<H_, 1>,
                         cudaFuncAttributeMaxDynamicSharedMemorySize, smem_bytes);

    const int nHH = 4 * H_ * H_;
    const int nIH0 = 4 * H_ * XP;
    // launch order matters for ncu (-s 5 -c 1): #6 must be gates_mma<H_,1>
    prep2_kernel<<<(nHH + nIH0 + 255) / 256, 256>>>(
        w_hh0, whh0t, nHH, H_, H_, w_ih0, wih0t, nIH0, V_, XP);     // 1
    prep2_kernel<<<(nHH + nHH + 255) / 256, 256>>>(
        w_hh1, whh1t, nHH, H_, H_, w_ih1, wih1t, nHH, H_, H_);      // 2
    init_kernel<<<(B_ * H_ + 255) / 256, 256>>>();                  // 3
    fc1_kernel<<<dim3(H_ / 64, B_ / 64), 256>>>(latent, fc1_w, fc1_b);  // 4

    for (int t = 0; t < S_; ++t) {
        const int p = t & 1;
        gates_mma<XP, 0><<<dim3(H_ / 32, B_ / 128), 256, smem_bytes>>>(
            p, whh0t, wih0t, b_ih0, b_hh0);                         // 5, 8, ...
        gates_mma<H_, 1><<<dim3(H_ / 32, B_ / 128), 256, smem_bytes>>>(
            p, whh1t, wih1t, b_ih1, b_hh1);                         // 6 <- ncu
        logits_kernel<<<B_ / LB, 256>>>(p, t, fc2_w, fc2_b, out);
    }
}

// round 10
// speedup vs baseline: 1.6696x; 1.6696x over previous
#include <cuda_runtime.h>
#include <cuda_fp16.h>
#include <cstdint>

#define B_ 2048
#define E_ 256
#define H_ 1024
#define V_ 42
#define S_ 100
#define XP 48            // padded x width (42 -> 48 halves = 3 full k16 tiles)

// ---------------- persistent device state (fp16 activations, fp32 cell) -----
__device__ __half g_x[B_ * XP];
__device__ __half g_h0[2][B_ * H_];
__device__ __half g_h1[2][B_ * H_];
__device__ float g_c0[B_ * H_];
__device__ float g_c1[B_ * H_];
__device__ __half g_whh0t[4 * H_ * H_];
__device__ __half g_wih0t[4 * H_ * XP];   // zero-padded cols 42..47
__device__ __half g_whh1t[4 * H_ * H_];
__device__ __half g_wih1t[4 * H_ * H_];

// ---------------- helpers ---------------------------------------------------
__device__ __forceinline__ float fsigm(float x) {
    return __fdividef(1.f, 1.f + __expf(-x));
}
__device__ __forceinline__ float ftanh(float x) {
    return __fdividef(2.f, 1.f + __expf(-2.f * x)) - 1.f;
}

// ---------------- prep + init (single launch) -------------------------------
__global__ void prep_all(const float* __restrict__ whh0, const float* __restrict__ wih0,
                         const float* __restrict__ whh1, const float* __restrict__ wih1)
{
    const int nHH = 4 * H_ * H_;
    const int nIH0 = 4 * H_ * XP;
    const int nBH = B_ * H_;
    int i = blockIdx.x * blockDim.x + threadIdx.x;
    if (i < nHH) {
        g_whh0t[i] = __float2half_rn(whh0[i]);
    } else if (i < 2 * nHH) {
        g_whh1t[i - nHH] = __float2half_rn(whh1[i - nHH]);
    } else if (i < 3 * nHH) {
        g_wih1t[i - 2 * nHH] = __float2half_rn(wih1[i - 2 * nHH]);
    } else if (i < 3 * nHH + nIH0) {
        int j = i - 3 * nHH;
        int r = j / XP, k = j - r * XP;
        g_wih0t[j] = (k < V_) ? __float2half_rn(wih0[r * V_ + k]) : __float2half_rn(0.f);
    } else if (i < 3 * nHH + nIH0 + nBH) {
        int j = i - 3 * nHH - nIH0;
        g_c0[j] = 0.f; g_c1[j] = 0.f;
        g_h1[0][j] = __float2half_rn(0.f);
    } else if (i < 3 * nHH + nIH0 + nBH + B_ * XP) {
        int j = i - 3 * nHH - nIH0 - nBH;
        g_x[j] = __float2half_rn(((j % XP) == V_ - 1) ? 1.f : 0.f);
    }
}

// ---------------- fc1: h0 = latent @ fc1_w^T + b (one-time, fp32 math) ------
__global__ __launch_bounds__(256) void fc1_kernel(
    const float* __restrict__ latent, const float* __restrict__ w,
    const float* __restrict__ bias)
{
    __shared__ float As[16][68];
    __shared__ float Ws[16][68];
    const int tid = threadIdx.x;
    const int bm = blockIdx.y * 64, bn = blockIdx.x * 64;
    const int r = tid >> 2, kq = (tid & 3) * 4;
    const int tx = tid & 15, ty = tid >> 4;
    float acc[4][4];
#pragma unroll
    for (int i = 0; i < 4; i++)
#pragma unroll
        for (int j = 0; j < 4; j++) acc[i][j] = 0.f;
    for (int k0 = 0; k0 < E_; k0 += 16) {
        float4 av = *reinterpret_cast<const float4*>(latent + (size_t)(bm + r) * E_ + k0 + kq);
        float4 wv = *reinterpret_cast<const float4*>(w + (size_t)(bn + r) * E_ + k0 + kq);
        __syncthreads();
        As[kq + 0][r] = av.x; As[kq + 1][r] = av.y; As[kq + 2][r] = av.z; As[kq + 3][r] = av.w;
        Ws[kq + 0][r] = wv.x; Ws[kq + 1][r] = wv.y; Ws[kq + 2][r] = wv.z; Ws[kq + 3][r] = wv.w;
        __syncthreads();
#pragma unroll
        for (int kk = 0; kk < 16; kk++) {
            float4 a = *(const float4*)&As[kk][ty * 4];
            float4 b = *(const float4*)&Ws[kk][tx * 4];
            float am[4] = {a.x, a.y, a.z, a.w};
            float bn2[4] = {b.x, b.y, b.z, b.w};
#pragma unroll
            for (int mi = 0; mi < 4; mi++)
#pragma unroll
                for (int ni = 0; ni < 4; ni++)
                    acc[mi][ni] = fmaf(am[mi], bn2[ni], acc[mi][ni]);
        }
    }
#pragma unroll
    for (int mi = 0; mi < 4; mi++) {
        int m = bm + ty * 4 + mi;
#pragma unroll
        for (int ni = 0; ni < 4; ni++)
            g_h0[0][(size_t)m * H_ + bn + tx * 4 + ni] =
                __float2half_rn(acc[mi][ni] + bias[bn + tx * 4 + ni]);
    }
}

// ---------------- FP16 tensor-core gates GEMM + fused LSTM cell --------------
// gates = h_prev @ W1^T + x @ W2^T via mma.sync.m16n8k16.f16 (fp32 accum).
// CTA tile 128m x 128j, j = nl*4 + g; 4-stage cp.async ring, one sync/tile.
#define NSTG 4
#define AS_STRIDE 24                      // halves; 48B rows -> conflict-free mma LDS
#define STG_H (128 * AS_STRIDE)           // halves per stage per array

template <int K2P, int LAYER>
__global__ __launch_bounds__(256, 2) void gates_mma(
    int p,
    const __half* __restrict__ W1,    // w_hh fp16 [4H, H]
    const __half* __restrict__ W2,    // w_ih fp16 [4H, K2P]
    const float* __restrict__ bih,
    const float* __restrict__ bhh)
{
    constexpr int T1 = H_ / 16;       // 64 k-tiles from hh
    constexpr int T2 = K2P / 16;      // 3 (layer0) or 64 (layer1)
    constexpr int T = T1 + T2;

    const __half* A1;
    const __half* A2;
    float* cbuf;
    __half* hout;
    if (LAYER == 0) { A1 = g_h0[p]; A2 = g_x;         cbuf = g_c0; hout = g_h0[p ^ 1]; }
    else            { A1 = g_h1[p]; A2 = g_h0[p ^ 1]; cbuf = g_c1; hout = g_h1[p ^ 1]; }
    const int strideA2 = (LAYER == 0) ? XP : H_;

    extern __shared__ __half sm[];
    __half (*As)[128][AS_STRIDE] = reinterpret_cast<__half (*)[128][AS_STRIDE]>(sm);
    __half (*Bs)[128][AS_STRIDE] =
        reinterpret_cast<__half (*)[128][AS_STRIDE]>(sm + NSTG * STG_H);

    const int tid = threadIdx.x;
    const int bm = blockIdx.y * 128;
    const int bn = blockIdx.x * 32;

    // ---- loader: 2 threads per row, one 16B cp.async per array each ----
    const int lrow = tid >> 1;            // 0..127
    const int lkq = (tid & 1) * 8;        // halves: 0 or 8
    const int wrow = (lrow & 3) * H_ + bn + (lrow >> 2);   // j = nl*4+g
    const __half* aRow1 = A1 + (size_t)(bm + lrow) * H_;
    const __half* aRow2 = A2 + (size_t)(bm + lrow) * strideA2;
    const __half* bRow1 = W1 + (size_t)wrow * H_;
    const __half* bRow2 = W2 + (size_t)wrow * K2P;

    auto issue = [&](int kt) {
        const int buf = kt & (NSTG - 1);
        const __half* as;
        const __half* bs;
        if (kt < T1) { int k = kt * 16 + lkq;        as = aRow1 + k; bs = bRow1 + k; }
        else         { int k = (kt - T1) * 16 + lkq; as = aRow2 + k; bs = bRow2 + k; }
        uint32_t da = (uint32_t)__cvta_generic_to_shared(&As[buf][lrow][lkq]);
        uint32_t db = (uint32_t)__cvta_generic_to_shared(&Bs[buf][lrow][lkq]);
        asm volatile(
            "cp.async.ca.shared.global [%0], [%1], 16;\n\t"
            "cp.async.ca.shared.global [%2], [%3], 16;\n\t"
            "cp.async.commit_group;\n\t"
            :: "r"(da), "l"(as), "r"(db), "l"(bs) : "memory");
    };

    // ---- mma mapping ----
    const int lane = tid & 31;
    const int wid = tid >> 5;
    const int wm = wid & 1;               // 2 warps over m
    const int wj = wid >> 1;              // 4 warps over j
    const int gid = lane >> 2, tig = lane & 3;

    float acc[4][4][4];
#pragma unroll
    for (int a = 0; a < 4; a++)
#pragma unroll
        for (int b = 0; b < 4; b++)
#pragma unroll
            for (int c = 0; c < 4; c++) acc[a][b][c] = 0.f;

    issue(0);
    issue(1);
    issue(2);

    for (int kt = 0; kt < T; ++kt) {
        const int buf = kt & (NSTG - 1);
        if (kt + 3 < T) {
            asm volatile("cp.async.wait_group 2;" ::: "memory");
            __syncthreads();
            issue(kt + 3);
        } else if (kt == T - 3) {
            asm volatile("cp.async.wait_group 2;" ::: "memory");
            __syncthreads();
        } else if (kt == T - 2) {
            asm volatile("cp.async.wait_group 1;" ::: "memory");
            __syncthreads();
        } else {
            asm volatile("cp.async.wait_group 0;" ::: "memory");
            __syncthreads();
        }
        uint32_t a[4][4], b[4][2];
#pragma unroll
        for (int mt = 0; mt < 4; mt++) {
            const int m0 = wm * 64 + mt * 16 + gid;
            a[mt][0] = *(const uint32_t*)&As[buf][m0][2 * tig];
            a[mt][1] = *(const uint32_t*)&As[buf][m0 + 8][2 * tig];
            a[mt][2] = *(const uint32_t*)&As[buf][m0][2 * tig + 8];
            a[mt][3] = *(const uint32_t*)&As[buf][m0 + 8][2 * tig + 8];
        }
#pragma unroll
        for (int nt = 0; nt < 4; nt++) {
            const int j0 = wj * 32 + nt * 8 + gid;
            b[nt][0] = *(const uint32_t*)&Bs[buf][j0][2 * tig];
            b[nt][1] = *(const uint32_t*)&Bs[buf][j0][2 * tig + 8];
        }
#pragma unroll
        for (int mt = 0; mt < 4; mt++)
#pragma unroll
            for (int nt = 0; nt < 4; nt++)
                asm volatile(
                    "mma.sync.aligned.m16n8k16.row.col.f32.f16.f16.f32 "
                    "{%0,%1,%2,%3}, {%4,%5,%6,%7}, {%8,%9}, {%0,%1,%2,%3};"
                    : "+f"(acc[mt][nt][0]), "+f"(acc[mt][nt][1]),
                      "+f"(acc[mt][nt][2]), "+f"(acc[mt][nt][3])
                    : "r"(a[mt][0]), "r"(a[mt][1]), "r"(a[mt][2]), "r"(a[mt][3]),
                      "r"(b[nt][0]), "r"(b[nt][1]));
    }

    // ---- fused LSTM cell epilogue via lane-pair shuffle (verified in R4) ----
    // tig even lanes ("A") hold (i_pre, f_pre); odd ("B") hold (g_pre, o_pre)
    const bool isA = (tig & 1) == 0;
    const int gl = (tig & 1) * 2;
#pragma unroll
    for (int nt = 0; nt < 4; nt++) {
        const int col = bn + wj * 8 + nt * 2 + (tig >> 1);
        const float bias0 = bih[gl * H_ + col] + bhh[gl * H_ + col];
        const float bias1 = bih[(gl + 1) * H_ + col] + bhh[(gl + 1) * H_ + col];
#pragma unroll
        for (int mt = 0; mt < 4; mt++) {
#pragma unroll
            for (int rh = 0; rh < 2; rh++) {
                const int m = bm + wm * 64 + mt * 16 + gid + rh * 8;
                const size_t off = (size_t)m * H_ + col;
                const float p0 = acc[mt][nt][rh * 2 + 0] + bias0;  // A: i, B: g
                const float p1 = acc[mt][nt][rh * 2 + 1] + bias1;  // A: f, B: o
                const float e = __expf(isA ? -p0 : -2.f * p0);
                const float q0 = __fdividef(isA ? 1.f : 2.f, 1.f + e) - (isA ? 0.f : 1.f);
                const float q1 = fsigm(p1);                        // A: sig(f), B: sig(o)
                const float partner = __shfl_xor_sync(0xffffffffu, q0, 1); // A: tanh(g)
                const float cold = isA ? cbuf[off] : 0.f;
                const float cn = fmaf(q1, cold, q0 * partner);     // A: sf*c + si*tg
                const float th = ftanh(cn);
                const float th2 = __shfl_xor_sync(0xffffffffu, th, 1);     // B: tanh(c_new)
                if (isA) cbuf[off] = cn;
                else     hout[off] = __float2half_rn(q1 * th2);    // B: sig(o)*tanh(cn)
            }
        }
    }
}

// ---------------- logits + softmax feedback ---------------------------------
#define LB 16
#define KC 64
__global__ __launch_bounds__(256) void logits_kernel(
    int p, int t,
    const float* __restrict__ w, const float* __restrict__ bias,
    float* __restrict__ out)
{
    const __half* h = g_h1[p ^ 1];
    __shared__ float hs[LB][KC + 1];
    __shared__ float ws[KC][48];
    __shared__ float ls[LB][48];
    const int tid = threadIdx.x;
    const int b0 = blockIdx.x * LB;
    const int r = tid >> 4, q = tid & 15;

    float acc0 = 0.f, acc1 = 0.f, acc2 = 0.f;
    for (int k0 = 0; k0 < H_; k0 += KC) {
        __syncthreads();
#pragma unroll
        for (int i = 0; i < 4; i++) {
            int idx = tid + i * 256;
            int rr = idx >> 6, kk = idx & 63;
            hs[rr][kk] = __half2float(h[(size_t)(b0 + rr) * H_ + k0 + kk]);
        }
        for (int idx = tid; idx < KC * V_; idx += 256) {
            int kk = idx / V_, v = idx - kk * V_;
            ws[kk][v] = w[(size_t)v * H_ + k0 + kk];
        }
        for (int idx = tid; idx < KC * (48 - V_); idx += 256) {
            int kk = idx / (48 - V_);
            ws[kk][V_ + idx % (48 - V_)] = 0.f;
        }
        __syncthreads();
#pragma unroll
        for (int kk = 0; kk < KC; kk++) {
            float a = hs[r][kk];
            acc0 = fmaf(a, ws[kk][q], acc0);
            acc1 = fmaf(a, ws[kk][q + 16], acc1);
            acc2 = fmaf(a, ws[kk][q + 32], acc2);
        }
    }
    const int b = b0 + r;
    const size_t ob = (size_t)b * S_ * V_ + (size_t)t * V_;
    float l0 = acc0 + bias[q];
    float l1 = acc1 + bias[q + 16];
    ls[r][q] = l0;      out[ob + q] = l0;
    ls[r][q + 16] = l1; out[ob + q + 16] = l1;
    if (q + 32 < V_) {
        float l2 = acc2 + bias[q + 32];
        ls[r][q + 32] = l2;
        out[ob + q + 32] = l2;
    }
    __syncthreads();
    if (tid < LB) {
        float mx = -1e30f;
#pragma unroll
        for (int v = 0; v < V_; v++) mx = fmaxf(mx, ls[tid][v]);
        float ev[V_];
        float sum = 0.f;
#pragma unroll
        for (int v = 0; v < V_; v++) {
            ev[v] = __expf(ls[tid][v] - mx);
            sum += ev[v];
        }
        float inv = __fdividef(1.f, sum);
        const int bb = b0 + tid;
#pragma unroll
        for (int v = 0; v < V_; v++)
            g_x[(size_t)bb * XP + v] = __float2half_rn(ev[v] * inv);
    }
}

// ---------------- driver ----------------------------------------------------
extern "C" void kernel_launch(void* const* d_in, const int* in_sizes, int n_in,
                              void* d_out, int out_size)
{
    const float* latent = (const float*)d_in[0];
    const float* fc1_w  = (const float*)d_in[1];
    const float* fc1_b  = (const float*)d_in[2];
    const float* fc2_w  = (const float*)d_in[3];
    const float* fc2_b  = (const float*)d_in[4];
    const float* w_ih0  = (const float*)d_in[5];
    const float* w_hh0  = (const float*)d_in[6];
    const float* b_ih0  = (const float*)d_in[7];
    const float* b_hh0  = (const float*)d_in[8];
    const float* w_ih1  = (const float*)d_in[9];
    const float* w_hh1  = (const float*)d_in[10];
    const float* b_ih1  = (const float*)d_in[11];
    const float* b_hh1  = (const float*)d_in[12];
    float* out = (float*)d_out;

    __half* whh0t; cudaGetSymbolAddress((void**)&whh0t, g_whh0t);
    __half* wih0t; cudaGetSymbolAddress((void**)&wih0t, g_wih0t);
    __half* whh1t; cudaGetSymbolAddress((void**)&whh1t, g_whh1t);
    __half* wih1t; cudaGetSymbolAddress((void**)&wih1t, g_wih1t);

    const int smem_bytes = NSTG * STG_H * 2 * (int)sizeof(__half);  // 48 KB
    cudaFuncSetAttribute(gates_mma<XP, 0>,
                         cudaFuncAttributeMaxDynamicSharedMemorySize, smem_bytes);
    cudaFuncSetAttribute(gates_mma<H_, 1>,
                         cudaFuncAttributeMaxDynamicSharedMemorySize, smem_bytes);

    const int nTot = 3 * 4 * H_ * H_ + 4 * H_ * XP + B_ * H_ + B_ * XP;
    // launch #4 of the run must be gates_mma<H_,1> (ncu capture slot)
    prep_all<<<(nTot + 255) / 256, 256>>>(w_hh0, w_ih0, w_hh1, w_ih1);      // 1
    fc1_kernel<<<dim3(H_ / 64, B_ / 64), 256>>>(latent, fc1_w, fc1_b);      // 2

    for (int t = 0; t < S_; ++t) {
        const int p = t & 1;
        gates_mma<XP, 0><<<dim3(H_ / 32, B_ / 128), 256, smem_bytes>>>(
            p, whh0t, wih0t, b_ih0, b_hh0);                                 // 3
        gates_mma<H_, 1><<<dim3(H_ / 32, B_ / 128), 256, smem_bytes>>>(
            p, whh1t, wih1t, b_ih1, b_hh1);                                 // 4 <- ncu
        logits_kernel<<<B_ / LB, 256>>>(p, t, fc2_w, fc2_b, out);
    }
}

// round 11
// speedup vs baseline: 2.2599x; 1.3536x over previous
#include <cuda_runtime.h>
#include <cuda_fp16.h>
#include <cstdint>

#define B_ 2048
#define E_ 256
#define H_ 1024
#define V_ 42
#define S_ 100
#define XP 48            // padded x width (42 -> 48 halves = 3 full k16 tiles)

// ---------------- persistent device state (fp16 activations, fp32 cell) -----
__device__ __half g_x[B_ * XP];
__device__ __half g_h0[2][B_ * H_];
__device__ __half g_h1[2][B_ * H_];
__device__ float g_c0[B_ * H_];
__device__ float g_c1[B_ * H_];
__device__ __half g_whh0t[4 * H_ * H_];
__device__ __half g_wih0t[4 * H_ * XP];   // zero-padded cols 42..47
__device__ __half g_whh1t[4 * H_ * H_];
__device__ __half g_wih1t[4 * H_ * H_];
__device__ float g_fc2t[H_ * 48];         // fc2_w transposed [k][v], v padded to 48

// ---------------- helpers ---------------------------------------------------
__device__ __forceinline__ float fsigm(float x) {
    return __fdividef(1.f, 1.f + __expf(-x));
}
__device__ __forceinline__ float ftanh(float x) {
    return __fdividef(2.f, 1.f + __expf(-2.f * x)) - 1.f;
}

// ---------------- prep + init (single launch) -------------------------------
__global__ void prep_all(const float* __restrict__ whh0, const float* __restrict__ wih0,
                         const float* __restrict__ whh1, const float* __restrict__ wih1,
                         const float* __restrict__ fc2w)
{
    const int nHH = 4 * H_ * H_;
    const int nIH0 = 4 * H_ * XP;
    const int nBH = B_ * H_;
    const int nBX = B_ * XP;
    const int nF = H_ * 48;
    int i = blockIdx.x * blockDim.x + threadIdx.x;
    if (i < nHH) {
        g_whh0t[i] = __float2half_rn(whh0[i]);
    } else if (i < 2 * nHH) {
        g_whh1t[i - nHH] = __float2half_rn(whh1[i - nHH]);
    } else if (i < 3 * nHH) {
        g_wih1t[i - 2 * nHH] = __float2half_rn(wih1[i - 2 * nHH]);
    } else if (i < 3 * nHH + nIH0) {
        int j = i - 3 * nHH;
        int r = j / XP, k = j - r * XP;
        g_wih0t[j] = (k < V_) ? __float2half_rn(wih0[r * V_ + k]) : __float2half_rn(0.f);
    } else if (i < 3 * nHH + nIH0 + nBH) {
        int j = i - 3 * nHH - nIH0;
        g_c0[j] = 0.f; g_c1[j] = 0.f;
        g_h1[0][j] = __float2half_rn(0.f);
    } else if (i < 3 * nHH + nIH0 + nBH + nBX) {
        int j = i - 3 * nHH - nIH0 - nBH;
        g_x[j] = __float2half_rn(((j % XP) == V_ - 1) ? 1.f : 0.f);
    } else if (i < 3 * nHH + nIH0 + nBH + nBX + nF) {
        int j = i - 3 * nHH - nIH0 - nBH - nBX;
        int k = j / 48, v = j - k * 48;
        g_fc2t[j] = (v < V_) ? fc2w[(size_t)v * H_ + k] : 0.f;
    }
}

// ---------------- fc1: h0 = latent @ fc1_w^T + b (one-time, fp32 math) ------
__global__ __launch_bounds__(256) void fc1_kernel(
    const float* __restrict__ latent, const float* __restrict__ w,
    const float* __restrict__ bias)
{
    __shared__ float As[16][68];
    __shared__ float Ws[16][68];
    const int tid = threadIdx.x;
    const int bm = blockIdx.y * 64, bn = blockIdx.x * 64;
    const int r = tid >> 2, kq = (tid & 3) * 4;
    const int tx = tid & 15, ty = tid >> 4;
    float acc[4][4];
#pragma unroll
    for (int i = 0; i < 4; i++)
#pragma unroll
        for (int j = 0; j < 4; j++) acc[i][j] = 0.f;
    for (int k0 = 0; k0 < E_; k0 += 16) {
        float4 av = *reinterpret_cast<const float4*>(latent + (size_t)(bm + r) * E_ + k0 + kq);
        float4 wv = *reinterpret_cast<const float4*>(w + (size_t)(bn + r) * E_ + k0 + kq);
        __syncthreads();
        As[kq + 0][r] = av.x; As[kq + 1][r] = av.y; As[kq + 2][r] = av.z; As[kq + 3][r] = av.w;
        Ws[kq + 0][r] = wv.x; Ws[kq + 1][r] = wv.y; Ws[kq + 2][r] = wv.z; Ws[kq + 3][r] = wv.w;
        __syncthreads();
#pragma unroll
        for (int kk = 0; kk < 16; kk++) {
            float4 a = *(const float4*)&As[kk][ty * 4];
            float4 b = *(const float4*)&Ws[kk][tx * 4];
            float am[4] = {a.x, a.y, a.z, a.w};
            float bn2[4] = {b.x, b.y, b.z, b.w};
#pragma unroll
            for (int mi = 0; mi < 4; mi++)
#pragma unroll
                for (int ni = 0; ni < 4; ni++)
                    acc[mi][ni] = fmaf(am[mi], bn2[ni], acc[mi][ni]);
        }
    }
#pragma unroll
    for (int mi = 0; mi < 4; mi++) {
        int m = bm + ty * 4 + mi;
#pragma unroll
        for (int ni = 0; ni < 4; ni++)
            g_h0[0][(size_t)m * H_ + bn + tx * 4 + ni] =
                __float2half_rn(acc[mi][ni] + bias[bn + tx * 4 + ni]);
    }
}

// ---------------- FP16 tensor-core gates GEMM + fused LSTM cell --------------
// gates = h_prev @ W1^T + x @ W2^T via mma.sync.m16n8k16.f16 (fp32 accum).
// Fragments loaded with ldmatrix.x4 (6 LDSM/warp/tile instead of 24 LDS).
#define NSTG 4
#define AS_STRIDE 24                      // halves; 48B rows -> conflict-free LDSM
#define STG_H (128 * AS_STRIDE)           // halves per stage per array

template <int K2P, int LAYER>
__global__ __launch_bounds__(256, 2) void gates_mma(
    int p,
    const __half* __restrict__ W1,    // w_hh fp16 [4H, H]
    const __half* __restrict__ W2,    // w_ih fp16 [4H, K2P]
    const float* __restrict__ bih,
    const float* __restrict__ bhh)
{
    constexpr int T1 = H_ / 16;       // 64 k-tiles from hh
    constexpr int T2 = K2P / 16;      // 3 (layer0) or 64 (layer1)
    constexpr int T = T1 + T2;

    const __half* A1;
    const __half* A2;
    float* cbuf;
    __half* hout;
    if (LAYER == 0) { A1 = g_h0[p]; A2 = g_x;         cbuf = g_c0; hout = g_h0[p ^ 1]; }
    else            { A1 = g_h1[p]; A2 = g_h0[p ^ 1]; cbuf = g_c1; hout = g_h1[p ^ 1]; }
    const int strideA2 = (LAYER == 0) ? XP : H_;

    extern __shared__ __half sm[];
    __half (*As)[128][AS_STRIDE] = reinterpret_cast<__half (*)[128][AS_STRIDE]>(sm);
    __half (*Bs)[128][AS_STRIDE] =
        reinterpret_cast<__half (*)[128][AS_STRIDE]>(sm + NSTG * STG_H);

    const int tid = threadIdx.x;
    const int bm = blockIdx.y * 128;
    const int bn = blockIdx.x * 32;

    // ---- loader: 2 threads per row, one 16B cp.async per array each ----
    const int lrow = tid >> 1;            // 0..127
    const int lkq = (tid & 1) * 8;        // halves: 0 or 8
    const int wrow = (lrow & 3) * H_ + bn + (lrow >> 2);   // j = nl*4+g
    const __half* aRow1 = A1 + (size_t)(bm + lrow) * H_;
    const __half* aRow2 = A2 + (size_t)(bm + lrow) * strideA2;
    const __half* bRow1 = W1 + (size_t)wrow * H_;
    const __half* bRow2 = W2 + (size_t)wrow * K2P;

    auto issue = [&](int kt) {
        const int buf = kt & (NSTG - 1);
        const __half* as;
        const __half* bs;
        if (kt < T1) { int k = kt * 16 + lkq;        as = aRow1 + k; bs = bRow1 + k; }
        else         { int k = (kt - T1) * 16 + lkq; as = aRow2 + k; bs = bRow2 + k; }
        uint32_t da = (uint32_t)__cvta_generic_to_shared(&As[buf][lrow][lkq]);
        uint32_t db = (uint32_t)__cvta_generic_to_shared(&Bs[buf][lrow][lkq]);
        asm volatile(
            "cp.async.ca.shared.global [%0], [%1], 16;\n\t"
            "cp.async.ca.shared.global [%2], [%3], 16;\n\t"
            "cp.async.commit_group;\n\t"
            :: "r"(da), "l"(as), "r"(db), "l"(bs) : "memory");
    };

    // ---- mma mapping ----
    const int lane = tid & 31;
    const int wid = tid >> 5;
    const int wm = wid & 1;               // 2 warps over m
    const int wj = wid >> 1;              // 4 warps over j
    const int gid = lane >> 2, tig = lane & 3;

    // ---- ldmatrix source addresses (precomputed; add stage offset in loop) --
    const int lmat = lane >> 3, lrow8 = lane & 7;
    const uint32_t as_base = (uint32_t)__cvta_generic_to_shared(&As[0][0][0]);
    const uint32_t bs_base = (uint32_t)__cvta_generic_to_shared(&Bs[0][0][0]);
    uint32_t aAddr[4], bAddr[2];
#pragma unroll
    for (int mt = 0; mt < 4; mt++) {
        // matrices: 0:(m0-7,k0-7) 1:(m8-15,k0-7) 2:(m0-7,k8-15) 3:(m8-15,k8-15)
        const int row = wm * 64 + mt * 16 + (lmat & 1) * 8 + lrow8;
        const int col = (lmat >> 1) * 8;
        aAddr[mt] = as_base + (uint32_t)(row * AS_STRIDE + col) * 2;
    }
#pragma unroll
    for (int g = 0; g < 2; g++) {
        // matrices: 0:(j0-7,k0-7) 1:(j0-7,k8-15) 2:(j8-15,k0-7) 3:(j8-15,k8-15)
        const int row = wj * 32 + g * 16 + (lmat >> 1) * 8 + lrow8;
        const int col = (lmat & 1) * 8;
        bAddr[g] = bs_base + (uint32_t)(row * AS_STRIDE + col) * 2;
    }

    float acc[4][4][4];
#pragma unroll
    for (int a = 0; a < 4; a++)
#pragma unroll
        for (int b = 0; b < 4; b++)
#pragma unroll
            for (int c = 0; c < 4; c++) acc[a][b][c] = 0.f;

    issue(0);
    issue(1);
    issue(2);

    for (int kt = 0; kt < T; ++kt) {
        const int buf = kt & (NSTG - 1);
        if (kt + 3 < T) {
            asm volatile("cp.async.wait_group 2;" ::: "memory");
            __syncthreads();
            issue(kt + 3);
        } else if (kt == T - 3) {
            asm volatile("cp.async.wait_group 2;" ::: "memory");
            __syncthreads();
        } else if (kt == T - 2) {
            asm volatile("cp.async.wait_group 1;" ::: "memory");
            __syncthreads();
        } else {
            asm volatile("cp.async.wait_group 0;" ::: "memory");
            __syncthreads();
        }
        const uint32_t so = (uint32_t)buf * (uint32_t)(STG_H * 2);
        uint32_t a[4][4], b[4][2];
#pragma unroll
        for (int mt = 0; mt < 4; mt++)
            asm volatile(
                "ldmatrix.sync.aligned.m8n8.x4.shared.b16 {%0,%1,%2,%3}, [%4];"
                : "=r"(a[mt][0]), "=r"(a[mt][1]), "=r"(a[mt][2]), "=r"(a[mt][3])
                : "r"(aAddr[mt] + so));
#pragma unroll
        for (int g = 0; g < 2; g++)
            asm volatile(
                "ldmatrix.sync.aligned.m8n8.x4.shared.b16 {%0,%1,%2,%3}, [%4];"
                : "=r"(b[2 * g][0]), "=r"(b[2 * g][1]),
                  "=r"(b[2 * g + 1][0]), "=r"(b[2 * g + 1][1])
                : "r"(bAddr[g] + so));
#pragma unroll
        for (int mt = 0; mt < 4; mt++)
#pragma unroll
            for (int nt = 0; nt < 4; nt++)
                asm volatile(
                    "mma.sync.aligned.m16n8k16.row.col.f32.f16.f16.f32 "
                    "{%0,%1,%2,%3}, {%4,%5,%6,%7}, {%8,%9}, {%0,%1,%2,%3};"
                    : "+f"(acc[mt][nt][0]), "+f"(acc[mt][nt][1]),
                      "+f"(acc[mt][nt][2]), "+f"(acc[mt][nt][3])
                    : "r"(a[mt][0]), "r"(a[mt][1]), "r"(a[mt][2]), "r"(a[mt][3]),
                      "r"(b[nt][0]), "r"(b[nt][1]));
    }

    // ---- fused LSTM cell epilogue via lane-pair shuffle (verified) ----
    const bool isA = (tig & 1) == 0;
    const int gl = (tig & 1) * 2;
#pragma unroll
    for (int nt = 0; nt < 4; nt++) {
        const int col = bn + wj * 8 + nt * 2 + (tig >> 1);
        const float bias0 = bih[gl * H_ + col] + bhh[gl * H_ + col];
        const float bias1 = bih[(gl + 1) * H_ + col] + bhh[(gl + 1) * H_ + col];
#pragma unroll
        for (int mt = 0; mt < 4; mt++) {
#pragma unroll
            for (int rh = 0; rh < 2; rh++) {
                const int m = bm + wm * 64 + mt * 16 + gid + rh * 8;
                const size_t off = (size_t)m * H_ + col;
                const float p0 = acc[mt][nt][rh * 2 + 0] + bias0;  // A: i, B: g
                const float p1 = acc[mt][nt][rh * 2 + 1] + bias1;  // A: f, B: o
                const float e = __expf(isA ? -p0 : -2.f * p0);
                const float q0 = __fdividef(isA ? 1.f : 2.f, 1.f + e) - (isA ? 0.f : 1.f);
                const float q1 = fsigm(p1);                        // A: sig(f), B: sig(o)
                const float partner = __shfl_xor_sync(0xffffffffu, q0, 1); // A: tanh(g)
                const float cold = isA ? cbuf[off] : 0.f;
                const float cn = fmaf(q1, cold, q0 * partner);     // A: sf*c + si*tg
                const float th = ftanh(cn);
                const float th2 = __shfl_xor_sync(0xffffffffu, th, 1);     // B: tanh(cn)
                if (isA) cbuf[off] = cn;
                else     hout[off] = __float2half_rn(q1 * th2);    // B: sig(o)*tanh(cn)
            }
        }
    }
}

// ---------------- logits + softmax feedback (3-stage cp.async pipeline) ------
#define LB 16
#define KC 64
#define LT (H_ / KC)                      // 16 k-iterations
__global__ __launch_bounds__(256) void logits_kernel(
    int p, int t,
    const float* __restrict__ bias,
    float* __restrict__ out)
{
    const __half* h = g_h1[p ^ 1];
    __shared__ __half hs[3][LB][72];      // 144B rows, 16B-aligned chunks
    __shared__ float ws[3][KC][48];       // transposed fc2 tile, coalesced
    __shared__ float ls[LB][48];
    const int tid = threadIdx.x;
    const int b0 = blockIdx.x * LB;
    const int r = tid >> 4, q = tid & 15;

    auto issue = [&](int it) {
        const int s = it % 3;
        const int k0 = it * KC;
        if (tid < 128) {
            const int rr = tid >> 3, c = tid & 7;
            uint32_t dst = (uint32_t)__cvta_generic_to_shared(&hs[s][rr][c * 8]);
            const __half* src = h + (size_t)(b0 + rr) * H_ + k0 + c * 8;
            asm volatile("cp.async.ca.shared.global [%0], [%1], 16;"
                         :: "r"(dst), "l"(src) : "memory");
        }
#pragma unroll
        for (int i = 0; i < 3; i++) {
            const int id = tid + i * 256;       // 0..767 = 64 rows x 12 chunks
            const int kk = id / 12, c = id - kk * 12;
            uint32_t dst = (uint32_t)__cvta_generic_to_shared(&ws[s][kk][c * 4]);
            const float* src = g_fc2t + (size_t)(k0 + kk) * 48 + c * 4;
            asm volatile("cp.async.ca.shared.global [%0], [%1], 16;"
                         :: "r"(dst), "l"(src) : "memory");
        }
        asm volatile("cp.async.commit_group;" ::: "memory");
    };

    float acc0 = 0.f, acc1 = 0.f, acc2 = 0.f;
    issue(0);
    issue(1);
    for (int it = 0; it < LT; ++it) {
        if (it + 2 < LT) {
            asm volatile("cp.async.wait_group 1;" ::: "memory");
            __syncthreads();
            issue(it + 2);
        } else if (it == LT - 2) {
            asm volatile("cp.async.wait_group 1;" ::: "memory");
            __syncthreads();
        } else {
            asm volatile("cp.async.wait_group 0;" ::: "memory");
            __syncthreads();
        }
        const int s = it % 3;
#pragma unroll
        for (int kk = 0; kk < KC; kk++) {
            const float a = __half2float(hs[s][r][kk]);
            acc0 = fmaf(a, ws[s][kk][q], acc0);
            acc1 = fmaf(a, ws[s][kk][q + 16], acc1);
            acc2 = fmaf(a, ws[s][kk][q + 32], acc2);   // pad cols are 0
        }
    }
    const int b = b0 + r;
    const size_t ob = (size_t)b * S_ * V_ + (size_t)t * V_;
    float l0 = acc0 + bias[q];
    float l1 = acc1 + bias[q + 16];
    ls[r][q] = l0;      out[ob + q] = l0;
    ls[r][q + 16] = l1; out[ob + q + 16] = l1;
    if (q + 32 < V_) {
        float l2 = acc2 + bias[q + 32];
        ls[r][q + 32] = l2;
        out[ob + q + 32] = l2;
    }
    __syncthreads();
    if (tid < LB) {
        float mx = -1e30f;
#pragma unroll
        for (int v = 0; v < V_; v++) mx = fmaxf(mx, ls[tid][v]);
        float ev[V_];
        float sum = 0.f;
#pragma unroll
        for (int v = 0; v < V_; v++) {
            ev[v] = __expf(ls[tid][v] - mx);
            sum += ev[v];
        }
        float inv = __fdividef(1.f, sum);
        const int bb = b0 + tid;
#pragma unroll
        for (int v = 0; v < V_; v++)
            g_x[(size_t)bb * XP + v] = __float2half_rn(ev[v] * inv);
    }
}

// ---------------- driver ----------------------------------------------------
extern "C" void kernel_launch(void* const* d_in, const int* in_sizes, int n_in,
                              void* d_out, int out_size)
{
    const float* latent = (const float*)d_in[0];
    const float* fc1_w  = (const float*)d_in[1];
    const float* fc1_b  = (const float*)d_in[2];
    const float* fc2_w  = (const float*)d_in[3];
    const float* fc2_b  = (const float*)d_in[4];
    const float* w_ih0  = (const float*)d_in[5];
    const float* w_hh0  = (const float*)d_in[6];
    const float* b_ih0  = (const float*)d_in[7];
    const float* b_hh0  = (const float*)d_in[8];
    const float* w_ih1  = (const float*)d_in[9];
    const float* w_hh1  = (const float*)d_in[10];
    const float* b_ih1  = (const float*)d_in[11];
    const float* b_hh1  = (const float*)d_in[12];
    float* out = (float*)d_out;

    __half* whh0t; cudaGetSymbolAddress((void**)&whh0t, g_whh0t);
    __half* wih0t; cudaGetSymbolAddress((void**)&wih0t, g_wih0t);
    __half* whh1t; cudaGetSymbolAddress((void**)&whh1t, g_whh1t);
    __half* wih1t; cudaGetSymbolAddress((void**)&wih1t, g_wih1t);

    const int smem_bytes = NSTG * STG_H * 2 * (int)sizeof(__half);  // 48 KB
    cudaFuncSetAttribute(gates_mma<XP, 0>,
                         cudaFuncAttributeMaxDynamicSharedMemorySize, smem_bytes);
    cudaFuncSetAttribute(gates_mma<H_, 1>,
                         cudaFuncAttributeMaxDynamicSharedMemorySize, smem_bytes);

    const int nTot = 3 * 4 * H_ * H_ + 4 * H_ * XP + B_ * H_ + B_ * XP + H_ * 48;
    // launch #4 of the run must be gates_mma<H_,1> (ncu capture slot)
    prep_all<<<(nTot + 255) / 256, 256>>>(w_hh0, w_ih0, w_hh1, w_ih1, fc2_w); // 1
    fc1_kernel<<<dim3(H_ / 64, B_ / 64), 256>>>(latent, fc1_w, fc1_b);        // 2

    for (int t = 0; t < S_; ++t) {
        const int p = t & 1;
        gates_mma<XP, 0><<<dim3(H_ / 32, B_ / 128), 256, smem_bytes>>>(
            p, whh0t, wih0t, b_ih0, b_hh0);                                   // 3
        gates_mma<H_, 1><<<dim3(H_ / 32, B_ / 128), 256, smem_bytes>>>(
            p, whh1t, wih1t, b_ih1, b_hh1);                                   // 4 <- ncu
        logits_kernel<<<B_ / LB, 256>>>(p, t, fc2_b, out);
    }
}

// round 13
// speedup vs baseline: 2.3024x; 1.0188x over previous
#include <cuda_runtime.h>
#include <cuda_fp16.h>
#include <cstdint>

#define B_ 2048
#define E_ 256
#define H_ 1024
#define V_ 42
#define S_ 100
#define XP 64            // padded x width (42 -> 64 halves = 2 full k32 chunks)

// ---------------- persistent device state (fp16 activations, fp32 cell) -----
__device__ __half g_x[B_ * XP];
__device__ __half g_h0[2][B_ * H_];
__device__ __half g_h1[2][B_ * H_];
__device__ float g_c0[B_ * H_];
__device__ float g_c1[B_ * H_];
__device__ __half g_whh0t[4 * H_ * H_];
__device__ __half g_wih0t[4 * H_ * XP];   // zero-padded cols 42..63
__device__ __half g_whh1t[4 * H_ * H_];
__device__ __half g_wih1t[4 * H_ * H_];
__device__ float g_fc2t[H_ * 48];         // fc2_w transposed [k][v], v padded to 48

// ---------------- helpers ---------------------------------------------------
__device__ __forceinline__ float fsigm(float x) {
    return __fdividef(1.f, 1.f + __expf(-x));
}
__device__ __forceinline__ float ftanh(float x) {
    return __fdividef(2.f, 1.f + __expf(-2.f * x)) - 1.f;
}

// ---------------- prep + init (single launch) -------------------------------
__global__ void prep_all(const float* __restrict__ whh0, const float* __restrict__ wih0,
                         const float* __restrict__ whh1, const float* __restrict__ wih1,
                         const float* __restrict__ fc2w)
{
    const int nHH = 4 * H_ * H_;
    const int nIH0 = 4 * H_ * XP;
    const int nBH = B_ * H_;
    const int nBX = B_ * XP;
    const int nF = H_ * 48;
    int i = blockIdx.x * blockDim.x + threadIdx.x;
    if (i < nHH) {
        g_whh0t[i] = __float2half_rn(whh0[i]);
    } else if (i < 2 * nHH) {
        g_whh1t[i - nHH] = __float2half_rn(whh1[i - nHH]);
    } else if (i < 3 * nHH) {
        g_wih1t[i - 2 * nHH] = __float2half_rn(wih1[i - 2 * nHH]);
    } else if (i < 3 * nHH + nIH0) {
        int j = i - 3 * nHH;
        int r = j >> 6, k = j & 63;
        g_wih0t[j] = (k < V_) ? __float2half_rn(wih0[r * V_ + k]) : __float2half_rn(0.f);
    } else if (i < 3 * nHH + nIH0 + nBH) {
        int j = i - 3 * nHH - nIH0;
        g_c0[j] = 0.f; g_c1[j] = 0.f;
        g_h1[0][j] = __float2half_rn(0.f);
    } else if (i < 3 * nHH + nIH0 + nBH + nBX) {
        int j = i - 3 * nHH - nIH0 - nBH;
        g_x[j] = __float2half_rn(((j & 63) == V_ - 1) ? 1.f : 0.f);
    } else if (i < 3 * nHH + nIH0 + nBH + nBX + nF) {
        int j = i - 3 * nHH - nIH0 - nBH - nBX;
        int k = j / 48, v = j - k * 48;
        g_fc2t[j] = (v < V_) ? fc2w[(size_t)v * H_ + k] : 0.f;
    }
}

// ---------------- fc1: h0 = latent @ fc1_w^T + b (one-time, fp32 math) ------
__global__ __launch_bounds__(256) void fc1_kernel(
    const float* __restrict__ latent, const float* __restrict__ w,
    const float* __restrict__ bias)
{
    __shared__ float As[16][68];
    __shared__ float Ws[16][68];
    const int tid = threadIdx.x;
    const int bm = blockIdx.y * 64, bn = blockIdx.x * 64;
    const int r = tid >> 2, kq = (tid & 3) * 4;
    const int tx = tid & 15, ty = tid >> 4;
    float acc[4][4];
#pragma unroll
    for (int i = 0; i < 4; i++)
#pragma unroll
        for (int j = 0; j < 4; j++) acc[i][j] = 0.f;
    for (int k0 = 0; k0 < E_; k0 += 16) {
        float4 av = *reinterpret_cast<const float4*>(latent + (size_t)(bm + r) * E_ + k0 + kq);
        float4 wv = *reinterpret_cast<const float4*>(w + (size_t)(bn + r) * E_ + k0 + kq);
        __syncthreads();
        As[kq + 0][r] = av.x; As[kq + 1][r] = av.y; As[kq + 2][r] = av.z; As[kq + 3][r] = av.w;
        Ws[kq + 0][r] = wv.x; Ws[kq + 1][r] = wv.y; Ws[kq + 2][r] = wv.z; Ws[kq + 3][r] = wv.w;
        __syncthreads();
#pragma unroll
        for (int kk = 0; kk < 16; kk++) {
            float4 a = *(const float4*)&As[kk][ty * 4];
            float4 b = *(const float4*)&Ws[kk][tx * 4];
            float am[4] = {a.x, a.y, a.z, a.w};
            float bn2[4] = {b.x, b.y, b.z, b.w};
#pragma unroll
            for (int mi = 0; mi < 4; mi++)
#pragma unroll
                for (int ni = 0; ni < 4; ni++)
                    acc[mi][ni] = fmaf(am[mi], bn2[ni], acc[mi][ni]);
        }
    }
#pragma unroll
    for (int mi = 0; mi < 4; mi++) {
        int m = bm + ty * 4 + mi;
#pragma unroll
        for (int ni = 0; ni < 4; ni++)
            g_h0[0][(size_t)m * H_ + bn + tx * 4 + ni] =
                __float2half_rn(acc[mi][ni] + bias[bn + tx * 4 + ni]);
    }
}

// ---------------- FP16 tensor-core gates GEMM + fused LSTM cell --------------
// gates = h_prev @ W1^T + x @ W2^T via mma.sync.m16n8k16.f16 (fp32 accum).
// k32 chunks, 3-stage cp.async.cg ring (L1-bypass fills), one barrier per k32.
#define NSTG 3
#define AS_STRIDE 40                      // halves; 80B rows -> conflict-free LDSM
#define STG_H (128 * AS_STRIDE)           // halves per stage per array

template <int K2P, int LAYER>
__global__ __launch_bounds__(256, 2) void gates_mma(
    int p,
    const __half* __restrict__ W1,    // w_hh fp16 [4H, H]
    const __half* __restrict__ W2,    // w_ih fp16 [4H, K2P]
    const float* __restrict__ bih,
    const float* __restrict__ bhh)
{
    constexpr int T1 = H_ / 32;       // 32 k32-chunks from hh
    constexpr int T2 = K2P / 32;      // 2 (layer0) or 32 (layer1)
    constexpr int T = T1 + T2;

    const __half* A1;
    const __half* A2;
    float* cbuf;
    __half* hout;
    if (LAYER == 0) { A1 = g_h0[p]; A2 = g_x;         cbuf = g_c0; hout = g_h0[p ^ 1]; }
    else            { A1 = g_h1[p]; A2 = g_h0[p ^ 1]; cbuf = g_c1; hout = g_h1[p ^ 1]; }
    const int strideA2 = (LAYER == 0) ? XP : H_;

    extern __shared__ __half sm[];
    __half (*As)[128][AS_STRIDE] = reinterpret_cast<__half (*)[128][AS_STRIDE]>(sm);
    __half (*Bs)[128][AS_STRIDE] =
        reinterpret_cast<__half (*)[128][AS_STRIDE]>(sm + NSTG * STG_H);

    const int tid = threadIdx.x;
    const int bm = blockIdx.y * 128;
    const int bn = blockIdx.x * 32;

    // ---- loader: 2 threads per row, 2x 16B cp.async.cg per array each ----
    const int lrow = tid >> 1;            // 0..127
    const int lkq = (tid & 1) * 16;       // halves: 0 or 16
    const int wrow = (lrow & 3) * H_ + bn + (lrow >> 2);   // j = nl*4+g
    const __half* aRow1 = A1 + (size_t)(bm + lrow) * H_;
    const __half* aRow2 = A2 + (size_t)(bm + lrow) * strideA2;
    const __half* bRow1 = W1 + (size_t)wrow * H_;
    const __half* bRow2 = W2 + (size_t)wrow * K2P;

    auto issue = [&](int kt) {
        const int buf = kt % NSTG;
        const __half* as;
        const __half* bs;
        if (kt < T1) { int k = kt * 32 + lkq;        as = aRow1 + k; bs = bRow1 + k; }
        else         { int k = (kt - T1) * 32 + lkq; as = aRow2 + k; bs = bRow2 + k; }
        uint32_t da = (uint32_t)__cvta_generic_to_shared(&As[buf][lrow][lkq]);
        uint32_t db = (uint32_t)__cvta_generic_to_shared(&Bs[buf][lrow][lkq]);
        asm volatile(
            "cp.async.cg.shared.global [%0], [%1], 16;\n\t"
            "cp.async.cg.shared.global [%2], [%3], 16;\n\t"
            "cp.async.cg.shared.global [%4], [%5], 16;\n\t"
            "cp.async.cg.shared.global [%6], [%7], 16;\n\t"
            "cp.async.commit_group;\n\t"
            :: "r"(da), "l"(as), "r"(da + 16), "l"(as + 8),
               "r"(db), "l"(bs), "r"(db + 16), "l"(bs + 8)
            : "memory");
    };

    // ---- mma mapping ----
    const int lane = tid & 31;
    const int wid = tid >> 5;
    const int wm = wid & 1;               // 2 warps over m
    const int wj = wid >> 1;              // 4 warps over j
    const int gid = lane >> 2, tig = lane & 3;

    // ---- ldmatrix base addresses (stage/sub-k offsets added in loop) ----
    const int lmat = lane >> 3, lrow8 = lane & 7;
    const uint32_t as_base = (uint32_t)__cvta_generic_to_shared(&As[0][0][0]);
    const uint32_t bs_base = (uint32_t)__cvta_generic_to_shared(&Bs[0][0][0]);
    uint32_t aAddr[4], bAddr[2];
#pragma unroll
    for (int mt = 0; mt < 4; mt++) {
        // x4 matrices: 0:(m0-7,k0-7) 1:(m8-15,k0-7) 2:(m0-7,k8-15) 3:(m8-15,k8-15)
        const int row = wm * 64 + mt * 16 + (lmat & 1) * 8 + lrow8;
        const int col = (lmat >> 1) * 8;
        aAddr[mt] = as_base + (uint32_t)(row * AS_STRIDE + col) * 2;
    }
#pragma unroll
    for (int g = 0; g < 2; g++) {
        // x4 matrices: 0:(j0-7,k0-7) 1:(j0-7,k8-15) 2:(j8-15,k0-7) 3:(j8-15,k8-15)
        const int row = wj * 32 + g * 16 + (lmat >> 1) * 8 + lrow8;
        const int col = (lmat & 1) * 8;
        bAddr[g] = bs_base + (uint32_t)(row * AS_STRIDE + col) * 2;
    }

    float acc[4][4][4];
#pragma unroll
    for (int a = 0; a < 4; a++)
#pragma unroll
        for (int b = 0; b < 4; b++)
#pragma unroll
            for (int c = 0; c < 4; c++) acc[a][b][c] = 0.f;

    issue(0);
    issue(1);

    for (int kt = 0; kt < T; ++kt) {
        const int buf = kt % NSTG;
        if (kt + 2 < T) {
            asm volatile("cp.async.wait_group 1;" ::: "memory");
            __syncthreads();
            issue(kt + 2);
        } else if (kt == T - 2) {
            asm volatile("cp.async.wait_group 1;" ::: "memory");
            __syncthreads();
        } else {
            asm volatile("cp.async.wait_group 0;" ::: "memory");
            __syncthreads();
        }
        const uint32_t so = (uint32_t)buf * (uint32_t)(STG_H * 2);
#pragma unroll
        for (int h = 0; h < 2; h++) {               // two k16 sub-tiles of the k32 chunk
            const uint32_t ko = so + (uint32_t)h * 32;  // +16 halves
            uint32_t a[4][4], b[4][2];
#pragma unroll
            for (int mt = 0; mt < 4; mt++)
                asm volatile(
                    "ldmatrix.sync.aligned.m8n8.x4.shared.b16 {%0,%1,%2,%3}, [%4];"
                    : "=r"(a[mt][0]), "=r"(a[mt][1]), "=r"(a[mt][2]), "=r"(a[mt][3])
                    : "r"(aAddr[mt] + ko));
#pragma unroll
            for (int g = 0; g < 2; g++)
                asm volatile(
                    "ldmatrix.sync.aligned.m8n8.x4.shared.b16 {%0,%1,%2,%3}, [%4];"
                    : "=r"(b[2 * g][0]), "=r"(b[2 * g][1]),
                      "=r"(b[2 * g + 1][0]), "=r"(b[2 * g + 1][1])
                    : "r"(bAddr[g] + ko));
#pragma unroll
            for (int mt = 0; mt < 4; mt++)
#pragma unroll
                for (int nt = 0; nt < 4; nt++)
                    asm volatile(
                        "mma.sync.aligned.m16n8k16.row.col.f32.f16.f16.f32 "
                        "{%0,%1,%2,%3}, {%4,%5,%6,%7}, {%8,%9}, {%0,%1,%2,%3};"
                        : "+f"(acc[mt][nt][0]), "+f"(acc[mt][nt][1]),
                          "+f"(acc[mt][nt][2]), "+f"(acc[mt][nt][3])
                        : "r"(a[mt][0]), "r"(a[mt][1]), "r"(a[mt][2]), "r"(a[mt][3]),
                          "r"(b[nt][0]), "r"(b[nt][1]));
        }
    }

    // ---- fused LSTM cell epilogue via lane-pair shuffle (verified) ----
    const bool isA = (tig & 1) == 0;
    const int gl = (tig & 1) * 2;
#pragma unroll
    for (int nt = 0; nt < 4; nt++) {
        const int col = bn + wj * 8 + nt * 2 + (tig >> 1);
        const float bias0 = bih[gl * H_ + col] + bhh[gl * H_ + col];
        const float bias1 = bih[(gl + 1) * H_ + col] + bhh[(gl + 1) * H_ + col];
#pragma unroll
        for (int mt = 0; mt < 4; mt++) {
#pragma unroll
            for (int rh = 0; rh < 2; rh++) {
                const int m = bm + wm * 64 + mt * 16 + gid + rh * 8;
                const size_t off = (size_t)m * H_ + col;
                const float p0 = acc[mt][nt][rh * 2 + 0] + bias0;  // A: i, B: g
                const float p1 = acc[mt][nt][rh * 2 + 1] + bias1;  // A: f, B: o
                const float e = __expf(isA ? -p0 : -2.f * p0);
                const float q0 = __fdividef(isA ? 1.f : 2.f, 1.f + e) - (isA ? 0.f : 1.f);
                const float q1 = fsigm(p1);                        // A: sig(f), B: sig(o)
                const float partner = __shfl_xor_sync(0xffffffffu, q0, 1); // A: tanh(g)
                const float cold = isA ? cbuf[off] : 0.f;
                const float cn = fmaf(q1, cold, q0 * partner);     // A: sf*c + si*tg
                const float th = ftanh(cn);
                const float th2 = __shfl_xor_sync(0xffffffffu, th, 1);     // B: tanh(cn)
                if (isA) cbuf[off] = cn;
                else     hout[off] = __float2half_rn(q1 * th2);    // B: sig(o)*tanh(cn)
            }
        }
    }
}

// ---------------- logits + softmax feedback (3-stage cp.async pipeline) ------
#define LB 16
#define KC 64
#define LT (H_ / KC)                      // 16 k-iterations
__global__ __launch_bounds__(256) void logits_kernel(
    int p, int t,
    const float* __restrict__ bias,
    float* __restrict__ out)
{
    const __half* h = g_h1[p ^ 1];
    __shared__ __half hs[3][LB][72];      // 144B rows, 16B-aligned chunks
    __shared__ float ws[3][KC][48];       // transposed fc2 tile, coalesced
    __shared__ float ls[LB][48];
    const int tid = threadIdx.x;
    const int b0 = blockIdx.x * LB;
    const int r = tid >> 4, q = tid & 15;

    auto issue = [&](int it) {
        const int s = it % 3;
        const int k0 = it * KC;
        if (tid < 128) {
            const int rr = tid >> 3, c = tid & 7;
            uint32_t dst = (uint32_t)__cvta_generic_to_shared(&hs[s][rr][c * 8]);
            const __half* src = h + (size_t)(b0 + rr) * H_ + k0 + c * 8;
            asm volatile("cp.async.ca.shared.global [%0], [%1], 16;"
                         :: "r"(dst), "l"(src) : "memory");
        }
#pragma unroll
        for (int i = 0; i < 3; i++) {
            const int id = tid + i * 256;       // 0..767 = 64 rows x 12 chunks
            const int kk = id / 12, c = id - kk * 12;
            uint32_t dst = (uint32_t)__cvta_generic_to_shared(&ws[s][kk][c * 4]);
            const float* src = g_fc2t + (size_t)(k0 + kk) * 48 + c * 4;
            asm volatile("cp.async.ca.shared.global [%0], [%1], 16;"
                         :: "r"(dst), "l"(src) : "memory");
        }
        asm volatile("cp.async.commit_group;" ::: "memory");
    };

    float acc0 = 0.f, acc1 = 0.f, acc2 = 0.f;
    issue(0);
    issue(1);
    for (int it = 0; it < LT; ++it) {
        if (it + 2 < LT) {
            asm volatile("cp.async.wait_group 1;" ::: "memory");
            __syncthreads();
            issue(it + 2);
        } else if (it == LT - 2) {
            asm volatile("cp.async.wait_group 1;" ::: "memory");
            __syncthreads();
        } else {
            asm volatile("cp.async.wait_group 0;" ::: "memory");
            __syncthreads();
        }
        const int s = it % 3;
#pragma unroll
        for (int kk = 0; kk < KC; kk++) {
            const float a = __half2float(hs[s][r][kk]);
            acc0 = fmaf(a, ws[s][kk][q], acc0);
            acc1 = fmaf(a, ws[s][kk][q + 16], acc1);
            acc2 = fmaf(a, ws[s][kk][q + 32], acc2);   // pad cols are 0
        }
    }
    const int b = b0 + r;
    const size_t ob = (size_t)b * S_ * V_ + (size_t)t * V_;
    float l0 = acc0 + bias[q];
    float l1 = acc1 + bias[q + 16];
    ls[r][q] = l0;      out[ob + q] = l0;
    ls[r][q + 16] = l1; out[ob + q + 16] = l1;
    if (q + 32 < V_) {
        float l2 = acc2 + bias[q + 32];
        ls[r][q + 32] = l2;
        out[ob + q + 32] = l2;
    }
    __syncthreads();
    if (tid < LB) {
        float mx = -1e30f;
#pragma unroll
        for (int v = 0; v < V_; v++) mx = fmaxf(mx, ls[tid][v]);
        float ev[V_];
        float sum = 0.f;
#pragma unroll
        for (int v = 0; v < V_; v++) {
            ev[v] = __expf(ls[tid][v] - mx);
            sum += ev[v];
        }
        float inv = __fdividef(1.f, sum);
        const int bb = b0 + tid;
#pragma unroll
        for (int v = 0; v < V_; v++)
            g_x[(size_t)bb * XP + v] = __float2half_rn(ev[v] * inv);
    }
}

// ---------------- driver ----------------------------------------------------
extern "C" void kernel_launch(void* const* d_in, const int* in_sizes, int n_in,
                              void* d_out, int out_size)
{
    const float* latent = (const float*)d_in[0];
    const float* fc1_w  = (const float*)d_in[1];
    const float* fc1_b  = (const float*)d_in[2];
    const float* fc2_w  = (const float*)d_in[3];
    const float* fc2_b  = (const float*)d_in[4];
    const float* w_ih0  = (const float*)d_in[5];
    const float* w_hh0  = (const float*)d_in[6];
    const float* b_ih0  = (const float*)d_in[7];
    const float* b_hh0  = (const float*)d_in[8];
    const float* w_ih1  = (const float*)d_in[9];
    const float* w_hh1  = (const float*)d_in[10];
    const float* b_ih1  = (const float*)d_in[11];
    const float* b_hh1  = (const float*)d_in[12];
    float* out = (float*)d_out;

    __half* whh0t; cudaGetSymbolAddress((void**)&whh0t, g_whh0t);
    __half* wih0t; cudaGetSymbolAddress((void**)&wih0t, g_wih0t);
    __half* whh1t; cudaGetSymbolAddress((void**)&whh1t, g_whh1t);
    __half* wih1t; cudaGetSymbolAddress((void**)&wih1t, g_wih1t);

    const int smem_bytes = NSTG * STG_H * 2 * (int)sizeof(__half);  // 60 KB
    cudaFuncSetAttribute(gates_mma<XP, 0>,
                         cudaFuncAttributeMaxDynamicSharedMemorySize, smem_bytes);
    cudaFuncSetAttribute(gates_mma<H_, 1>,
                         cudaFuncAttributeMaxDynamicSharedMemorySize, smem_bytes);

    const int nTot = 3 * 4 * H_ * H_ + 4 * H_ * XP + B_ * H_ + B_ * XP + H_ * 48;
    // launch #4 of the run must be gates_mma<H_,1> (ncu capture slot)
    prep_all<<<(nTot + 255) / 256, 256>>>(w_hh0, w_ih0, w_hh1, w_ih1, fc2_w); // 1
    fc1_kernel<<<dim3(H_ / 64, B_ / 64), 256>>>(latent, fc1_w, fc1_b);        // 2

    for (int t = 0; t < S_; ++t) {
        const int p = t & 1;
        gates_mma<XP, 0><<<dim3(H_ / 32, B_ / 128), 256, smem_bytes>>>(
            p, whh0t, wih0t, b_ih0, b_hh0);                                   // 3
        gates_mma<H_, 1><<<dim3(H_ / 32, B_ / 128), 256, smem_bytes>>>(
            p, whh1t, wih1t, b_ih1, b_hh1);                                   // 4 <- ncu
        logits_kernel<<<B_ / LB, 256>>>(p, t, fc2_b, out);
    }
}

// round 14
// speedup vs baseline: 2.3738x; 1.0310x over previous
#include <cuda_runtime.h>
#include <cuda_fp16.h>
#include <cstdint>

#define B_ 2048
#define E_ 256
#define H_ 1024
#define V_ 42
#define S_ 100
#define XP 64            // padded x width (42 -> 64 halves = 2 full k32 chunks)

// ---------------- persistent device state (fp16 activations, fp32 cell) -----
__device__ __half g_x[B_ * XP];
__device__ __half g_h0[2][B_ * H_];
__device__ __half g_h1[2][B_ * H_];
__device__ float g_c0[B_ * H_];
__device__ float g_c1[B_ * H_];
__device__ __half g_whh0t[4 * H_ * H_];
__device__ __half g_wih0t[4 * H_ * XP];   // zero-padded cols 42..63
__device__ __half g_whh1t[4 * H_ * H_];
__device__ __half g_wih1t[4 * H_ * H_];
__device__ float g_fc2t[H_ * 48];         // fc2_w transposed [k][v], v padded to 48

// ---------------- helpers ---------------------------------------------------
__device__ __forceinline__ float fsigm(float x) {
    return __fdividef(1.f, 1.f + __expf(-x));
}
__device__ __forceinline__ float ftanh(float x) {
    return __fdividef(2.f, 1.f + __expf(-2.f * x)) - 1.f;
}

// ---------------- prep + init (single launch) -------------------------------
__global__ void prep_all(const float* __restrict__ whh0, const float* __restrict__ wih0,
                         const float* __restrict__ whh1, const float* __restrict__ wih1,
                         const float* __restrict__ fc2w)
{
    const int nHH = 4 * H_ * H_;
    const int nIH0 = 4 * H_ * XP;
    const int nBH = B_ * H_;
    const int nBX = B_ * XP;
    const int nF = H_ * 48;
    int i = blockIdx.x * blockDim.x + threadIdx.x;
    if (i < nHH) {
        g_whh0t[i] = __float2half_rn(whh0[i]);
    } else if (i < 2 * nHH) {
        g_whh1t[i - nHH] = __float2half_rn(whh1[i - nHH]);
    } else if (i < 3 * nHH) {
        g_wih1t[i - 2 * nHH] = __float2half_rn(wih1[i - 2 * nHH]);
    } else if (i < 3 * nHH + nIH0) {
        int j = i - 3 * nHH;
        int r = j >> 6, k = j & 63;
        g_wih0t[j] = (k < V_) ? __float2half_rn(wih0[r * V_ + k]) : __float2half_rn(0.f);
    } else if (i < 3 * nHH + nIH0 + nBH) {
        int j = i - 3 * nHH - nIH0;
        g_c0[j] = 0.f; g_c1[j] = 0.f;
        g_h1[0][j] = __float2half_rn(0.f);
    } else if (i < 3 * nHH + nIH0 + nBH + nBX) {
        int j = i - 3 * nHH - nIH0 - nBH;
        g_x[j] = __float2half_rn(((j & 63) == V_ - 1) ? 1.f : 0.f);
    } else if (i < 3 * nHH + nIH0 + nBH + nBX + nF) {
        int j = i - 3 * nHH - nIH0 - nBH - nBX;
        int k = j / 48, v = j - k * 48;
        g_fc2t[j] = (v < V_) ? fc2w[(size_t)v * H_ + k] : 0.f;
    }
}

// ---------------- fc1: h0 = latent @ fc1_w^T + b (one-time, fp32 math) ------
__global__ __launch_bounds__(256) void fc1_kernel(
    const float* __restrict__ latent, const float* __restrict__ w,
    const float* __restrict__ bias)
{
    __shared__ float As[16][68];
    __shared__ float Ws[16][68];
    const int tid = threadIdx.x;
    const int bm = blockIdx.y * 64, bn = blockIdx.x * 64;
    const int r = tid >> 2, kq = (tid & 3) * 4;
    const int tx = tid & 15, ty = tid >> 4;
    float acc[4][4];
#pragma unroll
    for (int i = 0; i < 4; i++)
#pragma unroll
        for (int j = 0; j < 4; j++) acc[i][j] = 0.f;
    for (int k0 = 0; k0 < E_; k0 += 16) {
        float4 av = *reinterpret_cast<const float4*>(latent + (size_t)(bm + r) * E_ + k0 + kq);
        float4 wv = *reinterpret_cast<const float4*>(w + (size_t)(bn + r) * E_ + k0 + kq);
        __syncthreads();
        As[kq + 0][r] = av.x; As[kq + 1][r] = av.y; As[kq + 2][r] = av.z; As[kq + 3][r] = av.w;
        Ws[kq + 0][r] = wv.x; Ws[kq + 1][r] = wv.y; Ws[kq + 2][r] = wv.z; Ws[kq + 3][r] = wv.w;
        __syncthreads();
#pragma unroll
        for (int kk = 0; kk < 16; kk++) {
            float4 a = *(const float4*)&As[kk][ty * 4];
            float4 b = *(const float4*)&Ws[kk][tx * 4];
            float am[4] = {a.x, a.y, a.z, a.w};
            float bn2[4] = {b.x, b.y, b.z, b.w};
#pragma unroll
            for (int mi = 0; mi < 4; mi++)
#pragma unroll
                for (int ni = 0; ni < 4; ni++)
                    acc[mi][ni] = fmaf(am[mi], bn2[ni], acc[mi][ni]);
        }
    }
#pragma unroll
    for (int mi = 0; mi < 4; mi++) {
        int m = bm + ty * 4 + mi;
#pragma unroll
        for (int ni = 0; ni < 4; ni++)
            g_h0[0][(size_t)m * H_ + bn + tx * 4 + ni] =
                __float2half_rn(acc[mi][ni] + bias[bn + tx * 4 + ni]);
    }
}

// ---------------- FP16 tensor-core gates GEMM + fused LSTM cell --------------
// CTA tile 256m x 128j (j = nl*4 + g), 512 threads, 16 warps of 64m x 32j.
// Rationale: kernel is cp.async ISSUE-RATE bound; bigger tile cuts redundant
// loads 25% (A shared by 4 j-warp-cols, B by 4 m-warp-rows within one CTA).
#define NSTG 4
#define AS_STRIDE 40                      // halves; 80B rows -> conflict-free LDSM
#define A_STG (256 * AS_STRIDE)           // halves per A stage
#define B_STG (128 * AS_STRIDE)           // halves per B stage

template <int K2P, int LAYER>
__global__ __launch_bounds__(512, 1) void gates_mma(
    int p,
    const __half* __restrict__ W1,    // w_hh fp16 [4H, H]
    const __half* __restrict__ W2,    // w_ih fp16 [4H, K2P]
    const float* __restrict__ bih,
    const float* __restrict__ bhh)
{
    constexpr int T1 = H_ / 32;       // 32 k32-chunks from hh
    constexpr int T2 = K2P / 32;      // 2 (layer0) or 32 (layer1)
    constexpr int T = T1 + T2;

    const __half* A1;
    const __half* A2;
    float* cbuf;
    __half* hout;
    if (LAYER == 0) { A1 = g_h0[p]; A2 = g_x;         cbuf = g_c0; hout = g_h0[p ^ 1]; }
    else            { A1 = g_h1[p]; A2 = g_h0[p ^ 1]; cbuf = g_c1; hout = g_h1[p ^ 1]; }
    const int strideA2 = (LAYER == 0) ? XP : H_;

    extern __shared__ __half sm[];
    __half (*As)[256][AS_STRIDE] = reinterpret_cast<__half (*)[256][AS_STRIDE]>(sm);
    __half (*Bs)[128][AS_STRIDE] =
        reinterpret_cast<__half (*)[128][AS_STRIDE]>(sm + NSTG * A_STG);

    const int tid = threadIdx.x;
    const int bm = blockIdx.y * 256;
    const int bn = blockIdx.x * 32;

    // ---- loader: A = all 512 threads (2 ops), B = threads < 256 (2 ops) ----
    const int arow = tid >> 1;            // 0..255
    const int akq = (tid & 1) * 16;       // halves: 0 or 16
    const __half* aRow1 = A1 + (size_t)(bm + arow) * H_;
    const __half* aRow2 = A2 + (size_t)(bm + arow) * strideA2;
    const int brow = (tid & 255) >> 1;    // 0..127 (valid when tid < 256)
    const int bkq = (tid & 1) * 16;
    const int wrow = (brow & 3) * H_ + bn + (brow >> 2);   // j = nl*4+g
    const __half* bRow1 = W1 + (size_t)wrow * H_;
    const __half* bRow2 = W2 + (size_t)wrow * K2P;

    auto issue = [&](int kt) {
        const int buf = kt & (NSTG - 1);
        const __half* as;
        const __half* bs;
        if (kt < T1) { int k = kt * 32;        as = aRow1 + k + akq; bs = bRow1 + k + bkq; }
        else         { int k = (kt - T1) * 32; as = aRow2 + k + akq; bs = bRow2 + k + bkq; }
        uint32_t da = (uint32_t)__cvta_generic_to_shared(&As[buf][arow][akq]);
        asm volatile(
            "cp.async.cg.shared.global [%0], [%1], 16;\n\t"
            "cp.async.cg.shared.global [%2], [%3], 16;\n\t"
            :: "r"(da), "l"(as), "r"(da + 16), "l"(as + 8) : "memory");
        if (tid < 256) {
            uint32_t db = (uint32_t)__cvta_generic_to_shared(&Bs[buf][brow][bkq]);
            asm volatile(
                "cp.async.cg.shared.global [%0], [%1], 16;\n\t"
                "cp.async.cg.shared.global [%2], [%3], 16;\n\t"
                :: "r"(db), "l"(bs), "r"(db + 16), "l"(bs + 8) : "memory");
        }
        asm volatile("cp.async.commit_group;" ::: "memory");
    };

    // ---- mma mapping: 16 warps, warp tile 64m x 32j ----
    const int lane = tid & 31;
    const int wid = tid >> 5;
    const int wm = wid & 3;               // 4 warp-rows over m (64 each)
    const int wj = wid >> 2;              // 4 warp-cols over j (32 each)
    const int gid = lane >> 2, tig = lane & 3;

    // ---- ldmatrix base addresses (stage/sub-k offsets added in loop) ----
    const int lmat = lane >> 3, lrow8 = lane & 7;
    const uint32_t as_base = (uint32_t)__cvta_generic_to_shared(&As[0][0][0]);
    const uint32_t bs_base = (uint32_t)__cvta_generic_to_shared(&Bs[0][0][0]);
    uint32_t aAddr[4], bAddr[2];
#pragma unroll
    for (int mt = 0; mt < 4; mt++) {
        // x4 matrices: 0:(m0-7,k0-7) 1:(m8-15,k0-7) 2:(m0-7,k8-15) 3:(m8-15,k8-15)
        const int row = wm * 64 + mt * 16 + (lmat & 1) * 8 + lrow8;
        const int col = (lmat >> 1) * 8;
        aAddr[mt] = as_base + (uint32_t)(row * AS_STRIDE + col) * 2;
    }
#pragma unroll
    for (int g = 0; g < 2; g++) {
        // x4 matrices: 0:(j0-7,k0-7) 1:(j0-7,k8-15) 2:(j8-15,k0-7) 3:(j8-15,k8-15)
        const int row = wj * 32 + g * 16 + (lmat >> 1) * 8 + lrow8;
        const int col = (lmat & 1) * 8;
        bAddr[g] = bs_base + (uint32_t)(row * AS_STRIDE + col) * 2;
    }

    float acc[4][4][4];
#pragma unroll
    for (int a = 0; a < 4; a++)
#pragma unroll
        for (int b = 0; b < 4; b++)
#pragma unroll
            for (int c = 0; c < 4; c++) acc[a][b][c] = 0.f;

    issue(0);
    issue(1);
    issue(2);

    for (int kt = 0; kt < T; ++kt) {
        const int buf = kt & (NSTG - 1);
        if (kt + 3 < T) {
            asm volatile("cp.async.wait_group 2;" ::: "memory");
            __syncthreads();
            issue(kt + 3);
        } else if (kt == T - 3) {
            asm volatile("cp.async.wait_group 2;" ::: "memory");
            __syncthreads();
        } else if (kt == T - 2) {
            asm volatile("cp.async.wait_group 1;" ::: "memory");
            __syncthreads();
        } else {
            asm volatile("cp.async.wait_group 0;" ::: "memory");
            __syncthreads();
        }
        const uint32_t soA = (uint32_t)buf * (uint32_t)(A_STG * 2);
        const uint32_t soB = (uint32_t)buf * (uint32_t)(B_STG * 2);
#pragma unroll
        for (int h = 0; h < 2; h++) {               // two k16 sub-tiles of the k32 chunk
            const uint32_t ho = (uint32_t)h * 32;   // +16 halves
            uint32_t a[4][4], b[4][2];
#pragma unroll
            for (int mt = 0; mt < 4; mt++)
                asm volatile(
                    "ldmatrix.sync.aligned.m8n8.x4.shared.b16 {%0,%1,%2,%3}, [%4];"
                    : "=r"(a[mt][0]), "=r"(a[mt][1]), "=r"(a[mt][2]), "=r"(a[mt][3])
                    : "r"(aAddr[mt] + soA + ho));
#pragma unroll
            for (int g = 0; g < 2; g++)
                asm volatile(
                    "ldmatrix.sync.aligned.m8n8.x4.shared.b16 {%0,%1,%2,%3}, [%4];"
                    : "=r"(b[2 * g][0]), "=r"(b[2 * g][1]),
                      "=r"(b[2 * g + 1][0]), "=r"(b[2 * g + 1][1])
                    : "r"(bAddr[g] + soB + ho));
#pragma unroll
            for (int mt = 0; mt < 4; mt++)
#pragma unroll
                for (int nt = 0; nt < 4; nt++)
                    asm volatile(
                        "mma.sync.aligned.m16n8k16.row.col.f32.f16.f16.f32 "
                        "{%0,%1,%2,%3}, {%4,%5,%6,%7}, {%8,%9}, {%0,%1,%2,%3};"
                        : "+f"(acc[mt][nt][0]), "+f"(acc[mt][nt][1]),
                          "+f"(acc[mt][nt][2]), "+f"(acc[mt][nt][3])
                        : "r"(a[mt][0]), "r"(a[mt][1]), "r"(a[mt][2]), "r"(a[mt][3]),
                          "r"(b[nt][0]), "r"(b[nt][1]));
        }
    }

    // ---- fused LSTM cell epilogue via lane-pair shuffle (verified) ----
    const bool isA = (tig & 1) == 0;
    const int gl = (tig & 1) * 2;
#pragma unroll
    for (int nt = 0; nt < 4; nt++) {
        const int col = bn + wj * 8 + nt * 2 + (tig >> 1);
        const float bias0 = bih[gl * H_ + col] + bhh[gl * H_ + col];
        const float bias1 = bih[(gl + 1) * H_ + col] + bhh[(gl + 1) * H_ + col];
#pragma unroll
        for (int mt = 0; mt < 4; mt++) {
#pragma unroll
            for (int rh = 0; rh < 2; rh++) {
                const int m = bm + wm * 64 + mt * 16 + gid + rh * 8;
                const size_t off = (size_t)m * H_ + col;
                const float p0 = acc[mt][nt][rh * 2 + 0] + bias0;  // A: i, B: g
                const float p1 = acc[mt][nt][rh * 2 + 1] + bias1;  // A: f, B: o
                const float e = __expf(isA ? -p0 : -2.f * p0);
                const float q0 = __fdividef(isA ? 1.f : 2.f, 1.f + e) - (isA ? 0.f : 1.f);
                const float q1 = fsigm(p1);                        // A: sig(f), B: sig(o)
                const float partner = __shfl_xor_sync(0xffffffffu, q0, 1); // A: tanh(g)
                const float cold = isA ? cbuf[off] : 0.f;
                const float cn = fmaf(q1, cold, q0 * partner);     // A: sf*c + si*tg
                const float th = ftanh(cn);
                const float th2 = __shfl_xor_sync(0xffffffffu, th, 1);     // B: tanh(cn)
                if (isA) cbuf[off] = cn;
                else     hout[off] = __float2half_rn(q1 * th2);    // B: sig(o)*tanh(cn)
            }
        }
    }
}

// ---------------- logits + softmax feedback (3-stage cp.async pipeline) ------
#define LB 16
#define KC 64
#define LT (H_ / KC)                      // 16 k-iterations
__global__ __launch_bounds__(256) void logits_kernel(
    int p, int t,
    const float* __restrict__ bias,
    float* __restrict__ out)
{
    const __half* h = g_h1[p ^ 1];
    __shared__ __half hs[3][LB][72];      // 144B rows, 16B-aligned chunks
    __shared__ float ws[3][KC][48];       // transposed fc2 tile, coalesced
    __shared__ float ls[LB][48];
    const int tid = threadIdx.x;
    const int b0 = blockIdx.x * LB;
    const int r = tid >> 4, q = tid & 15;

    auto issue = [&](int it) {
        const int s = it % 3;
        const int k0 = it * KC;
        if (tid < 128) {
            const int rr = tid >> 3, c = tid & 7;
            uint32_t dst = (uint32_t)__cvta_generic_to_shared(&hs[s][rr][c * 8]);
            const __half* src = h + (size_t)(b0 + rr) * H_ + k0 + c * 8;
            asm volatile("cp.async.ca.shared.global [%0], [%1], 16;"
                         :: "r"(dst), "l"(src) : "memory");
        }
#pragma unroll
        for (int i = 0; i < 3; i++) {
            const int id = tid + i * 256;       // 0..767 = 64 rows x 12 chunks
            const int kk = id / 12, c = id - kk * 12;
            uint32_t dst = (uint32_t)__cvta_generic_to_shared(&ws[s][kk][c * 4]);
            const float* src = g_fc2t + (size_t)(k0 + kk) * 48 + c * 4;
            asm volatile("cp.async.ca.shared.global [%0], [%1], 16;"
                         :: "r"(dst), "l"(src) : "memory");
        }
        asm volatile("cp.async.commit_group;" ::: "memory");
    };

    float acc0 = 0.f, acc1 = 0.f, acc2 = 0.f;
    issue(0);
    issue(1);
    for (int it = 0; it < LT; ++it) {
        if (it + 2 < LT) {
            asm volatile("cp.async.wait_group 1;" ::: "memory");
            __syncthreads();
            issue(it + 2);
        } else if (it == LT - 2) {
            asm volatile("cp.async.wait_group 1;" ::: "memory");
            __syncthreads();
        } else {
            asm volatile("cp.async.wait_group 0;" ::: "memory");
            __syncthreads();
        }
        const int s = it % 3;
#pragma unroll
        for (int kk = 0; kk < KC; kk++) {
            const float a = __half2float(hs[s][r][kk]);
            acc0 = fmaf(a, ws[s][kk][q], acc0);
            acc1 = fmaf(a, ws[s][kk][q + 16], acc1);
            acc2 = fmaf(a, ws[s][kk][q + 32], acc2);   // pad cols are 0
        }
    }
    const int b = b0 + r;
    const size_t ob = (size_t)b * S_ * V_ + (size_t)t * V_;
    float l0 = acc0 + bias[q];
    float l1 = acc1 + bias[q + 16];
    ls[r][q] = l0;      out[ob + q] = l0;
    ls[r][q + 16] = l1; out[ob + q + 16] = l1;
    if (q + 32 < V_) {
        float l2 = acc2 + bias[q + 32];
        ls[r][q + 32] = l2;
        out[ob + q + 32] = l2;
    }
    __syncthreads();
    if (tid < LB) {
        float mx = -1e30f;
#pragma unroll
        for (int v = 0; v < V_; v++) mx = fmaxf(mx, ls[tid][v]);
        float ev[V_];
        float sum = 0.f;
#pragma unroll
        for (int v = 0; v < V_; v++) {
            ev[v] = __expf(ls[tid][v] - mx);
            sum += ev[v];
        }
        float inv = __fdividef(1.f, sum);
        const int bb = b0 + tid;
#pragma unroll
        for (int v = 0; v < V_; v++)
            g_x[(size_t)bb * XP + v] = __float2half_rn(ev[v] * inv);
    }
}

// ---------------- driver ----------------------------------------------------
extern "C" void kernel_launch(void* const* d_in, const int* in_sizes, int n_in,
                              void* d_out, int out_size)
{
    const float* latent = (const float*)d_in[0];
    const float* fc1_w  = (const float*)d_in[1];
    const float* fc1_b  = (const float*)d_in[2];
    const float* fc2_w  = (const float*)d_in[3];
    const float* fc2_b  = (const float*)d_in[4];
    const float* w_ih0  = (const float*)d_in[5];
    const float* w_hh0  = (const float*)d_in[6];
    const float* b_ih0  = (const float*)d_in[7];
    const float* b_hh0  = (const float*)d_in[8];
    const float* w_ih1  = (const float*)d_in[9];
    const float* w_hh1  = (const float*)d_in[10];
    const float* b_ih1  = (const float*)d_in[11];
    const float* b_hh1  = (const float*)d_in[12];
    float* out = (float*)d_out;

    __half* whh0t; cudaGetSymbolAddress((void**)&whh0t, g_whh0t);
    __half* wih0t; cudaGetSymbolAddress((void**)&wih0t, g_wih0t);
    __half* whh1t; cudaGetSymbolAddress((void**)&whh1t, g_whh1t);
    __half* wih1t; cudaGetSymbolAddress((void**)&wih1t, g_wih1t);

    const int smem_bytes = NSTG * (A_STG + B_STG) * (int)sizeof(__half);  // 120 KB
    cudaFuncSetAttribute(gates_mma<XP, 0>,
                         cudaFuncAttributeMaxDynamicSharedMemorySize, smem_bytes);
    cudaFuncSetAttribute(gates_mma<H_, 1>,
                         cudaFuncAttributeMaxDynamicSharedMemorySize, smem_bytes);

    const int nTot = 3 * 4 * H_ * H_ + 4 * H_ * XP + B_ * H_ + B_ * XP + H_ * 48;
    // launch #4 of the run must be gates_mma<H_,1> (ncu capture slot)
    prep_all<<<(nTot + 255) / 256, 256>>>(w_hh0, w_ih0, w_hh1, w_ih1, fc2_w); // 1
    fc1_kernel<<<dim3(H_ / 64, B_ / 64), 256>>>(latent, fc1_w, fc1_b);        // 2

    for (int t = 0; t < S_; ++t) {
        const int p = t & 1;
        gates_mma<XP, 0><<<dim3(H_ / 32, B_ / 256), 512, smem_bytes>>>(
            p, whh0t, wih0t, b_ih0, b_hh0);                                   // 3
        gates_mma<H_, 1><<<dim3(H_ / 32, B_ / 256), 512, smem_bytes>>>(
            p, whh1t, wih1t, b_ih1, b_hh1);                                   // 4 <- ncu
        logits_kernel<<<B_ / LB, 256>>>(p, t, fc2_b, out);
    }
}